// round 10
// baseline (speedup 1.0000x reference)
#include <cuda_runtime.h>
#include <cuda_fp16.h>
#include <math.h>
#include <float.h>
#include <stdint.h>

// Problem constants
#define BATCH 32
#define LSEQ  2048
#define EDIM  1024
#define NHEAD 16
#define DHEAD 64
#define HD    (NHEAD * DHEAD)     // 1024
#define ROWS  (BATCH * LSEQ)      // 65536
#define FLAT  (LSEQ * EDIM)       // 2097152
#define NCLS  2

#define SMEM_SWIZZLE_128B(byte_offset) \
    ((byte_offset) ^ (((byte_offset) >> 3) & 0x70))

__device__ __forceinline__ uint32_t smem_to_u32(const void* smem_ptr) {
    uint32_t addr;
    asm("{ .reg .u64 tmp; cvta.to.shared.u64 tmp, %1; cvt.u32.u64 %0, tmp; }"
        : "=r"(addr) : "l"(smem_ptr));
    return addr;
}

__device__ __forceinline__ void cp_async16(uint32_t smem_addr, const void* gptr) {
    asm volatile("cp.async.cg.shared.global [%0], [%1], 16;"
                 :: "r"(smem_addr), "l"(gptr) : "memory");
}
__device__ __forceinline__ void cp_commit() {
    asm volatile("cp.async.commit_group;" ::: "memory");
}

__device__ __forceinline__ void ldmx4(uint32_t* r, uint32_t addr) {
    asm volatile("ldmatrix.sync.aligned.m8n8.x4.shared.b16 {%0,%1,%2,%3}, [%4];"
                 : "=r"(r[0]), "=r"(r[1]), "=r"(r[2]), "=r"(r[3]) : "r"(addr));
}
__device__ __forceinline__ void ldmx4t(uint32_t* r, uint32_t addr) {
    asm volatile("ldmatrix.sync.aligned.m8n8.x4.trans.shared.b16 {%0,%1,%2,%3}, [%4];"
                 : "=r"(r[0]), "=r"(r[1]), "=r"(r[2]), "=r"(r[3]) : "r"(addr));
}

// f16 inputs, f16 accumulator
__device__ __forceinline__ void mma16816h(uint32_t* c, const uint32_t* a, const uint32_t* b) {
    asm volatile(
        "mma.sync.aligned.m16n8k16.row.col.f16.f16.f16.f16 "
        "{%0,%1}, {%2,%3,%4,%5}, {%6,%7}, {%0,%1};"
        : "+r"(c[0]), "+r"(c[1])
        : "r"(a[0]), "r"(a[1]), "r"(a[2]), "r"(a[3]), "r"(b[0]), "r"(b[1]));
}

// f16 inputs, f32 accumulator (attention)
__device__ __forceinline__ void mma16816f(float* c, const uint32_t* a, const uint32_t* b) {
    asm volatile(
        "mma.sync.aligned.m16n8k16.row.col.f32.f16.f16.f32 "
        "{%0,%1,%2,%3}, {%4,%5,%6,%7}, {%8,%9}, {%0,%1,%2,%3};"
        : "+f"(c[0]), "+f"(c[1]), "+f"(c[2]), "+f"(c[3])
        : "r"(a[0]), "r"(a[1]), "r"(a[2]), "r"(a[3]), "r"(b[0]), "r"(b[1]));
}

// ---------------------------------------------------------------------------
// Device-global scratch (f16)
// ---------------------------------------------------------------------------
__device__ __half g_hb[(size_t)ROWS * EDIM];     // 128 MB
__device__ __half g_qb[(size_t)ROWS * HD];       // q, then att (in place)
__device__ __half g_kb[(size_t)ROWS * HD];
__device__ __half g_vb[(size_t)ROWS * HD];
__device__ __half g_ob[(size_t)ROWS * EDIM];
__device__ __half g_wqkv[(size_t)3 * HD * EDIM]; // fused Wq^T|Wk^T|Wv^T
__device__ __half g_wo[(size_t)EDIM * HD];
__device__ double g_logits[BATCH * NCLS];

// ---------------------------------------------------------------------------
// 1) Embedding gather -> f16
// ---------------------------------------------------------------------------
__global__ __launch_bounds__(256) void gather_kernel(
    const int* __restrict__ x, const float* __restrict__ emb)
{
    int row = blockIdx.x;
    int v = x[row];
    int t = threadIdx.x;
    float4 f = ((const float4*)(emb + (size_t)v * EDIM))[t];
    __half2 lo = __floats2half2_rn(f.x, f.y);
    __half2 hi = __floats2half2_rn(f.z, f.w);
    uint2 p;
    p.x = *(uint32_t*)&lo;
    p.y = *(uint32_t*)&hi;
    ((uint2*)(g_hb + (size_t)row * EDIM))[t] = p;
}

// ---------------------------------------------------------------------------
// 1b) Fused weight transpose + convert (grid.z selects which weight)
// ---------------------------------------------------------------------------
__global__ __launch_bounds__(256) void transpose_all_kernel(
    const float* __restrict__ Wq, const float* __restrict__ Wkv,
    const float* __restrict__ Wo,
    __half* __restrict__ wqkv, __half* __restrict__ wo)
{
    __shared__ float tile[32][33];
    const float* in; int ldin, coloff; __half* out;
    switch (blockIdx.z) {
        case 0: in = Wq;  ldin = HD;     coloff = 0;  out = wqkv;                         break;
        case 1: in = Wkv; ldin = 2 * HD; coloff = 0;  out = wqkv + (size_t)HD * EDIM;     break;
        case 2: in = Wkv; ldin = 2 * HD; coloff = HD; out = wqkv + (size_t)2 * HD * EDIM; break;
        default: in = Wo; ldin = EDIM;   coloff = 0;  out = wo;                           break;
    }
    int bx = blockIdx.x * 32;  // n block
    int by = blockIdx.y * 32;  // k block
    int tx = threadIdx.x & 31;
    int ty = threadIdx.x >> 5;
    for (int i = ty; i < 32; i += 8)
        tile[i][tx] = in[(size_t)(by + i) * ldin + coloff + bx + tx];
    __syncthreads();
    for (int i = ty; i < 32; i += 8)
        out[(size_t)(bx + i) * 1024 + by + tx] = __float2half(tile[tx][i]);
}

// ---------------------------------------------------------------------------
// 2) PERSISTENT f16 tensor-core GEMM. CTA tile 128x128, 256 threads,
//    3-stage cp.async ring that runs CONTINUOUSLY across tile boundaries
//    (loads for the next tile issue during the tail/epilogue of the current).
// ---------------------------------------------------------------------------
#define MT 128
#define NT 128
#define A_BYTES (MT * 128)          // 16 KB per K-chunk of 64
#define B_BYTES (NT * 128)          // 16 KB
#define NCHUNKS 16
#define STAGES 3
#define GEMM_SMEM (STAGES * (A_BYTES + B_BYTES) + 1024)   // 99328

__device__ __forceinline__ void load_chunk(
    uint32_t abuf, uint32_t bbuf,
    const char* Abase, const char* Bbase, int c, int t)
{
#pragma unroll
    for (int i = 0; i < 4; i++) {
        int seg = t + 256 * i;
        int r = seg >> 3, s = seg & 7;
        uint32_t off = SMEM_SWIZZLE_128B((uint32_t)(r * 128 + s * 16));
        cp_async16(abuf + off, Abase + (size_t)r * 2048 + c * 128 + s * 16);
    }
#pragma unroll
    for (int i = 0; i < 4; i++) {
        int seg = t + 256 * i;
        int r = seg >> 3, s = seg & 7;
        uint32_t off = SMEM_SWIZZLE_128B((uint32_t)(r * 128 + s * 16));
        cp_async16(bbuf + off, Bbase + (size_t)r * 2048 + c * 128 + s * 16);
    }
}

__device__ __forceinline__ void tile_bases(
    int tileidx, int nxblocks,
    const __half* A, const __half* Bt,
    const char*& Ab, const char*& Bb, int& bx, int& by)
{
    int group = tileidx / (nxblocks * 8);
    int rem   = tileidx % (nxblocks * 8);
    bx = rem % nxblocks;
    by = group * 8 + (rem / nxblocks);
    Ab = (const char*)(A + (size_t)by * MT * 1024);
    Bb = (const char*)(Bt + (size_t)bx * NT * 1024);
}

template<bool RES>
__global__ __launch_bounds__(256, 2) void gemm_f16_persist(
    const __half* __restrict__ A,
    const __half* __restrict__ Bt,
    const __half* __restrict__ Res,
    __half* __restrict__ D0,
    __half* __restrict__ D1,
    __half* __restrict__ D2,
    int nxblocks, int ntiles)
{
    extern __shared__ char smem[];
    uint32_t base = (smem_to_u32(smem) + 1023) & ~1023u;
    uint32_t a_sm[STAGES], b_sm[STAGES];
#pragma unroll
    for (int s = 0; s < STAGES; s++) {
        a_sm[s] = base + s * (A_BYTES + B_BYTES);
        b_sm[s] = a_sm[s] + A_BYTES;
    }

    int t = threadIdx.x;
    int wid = t >> 5, lane = t & 31;
    int mwarp0 = (wid & 3) * 32;
    int nwarp0 = (wid >> 2) * 64;

    // per-lane ldmatrix address components (tile-independent; smem-relative)
    int g = lane & 7, sel = lane >> 3;
    int mA = mwarp0 + g + (sel & 1) * 8;
    uint32_t aRow[2] = { (uint32_t)(mA * 128), (uint32_t)((mA + 16) * 128) };
    uint32_t aKb = (uint32_t)((sel >> 1) * 16);
    uint32_t aX  = (uint32_t)((mA & 7) << 4);

    int nB = nwarp0 + g + ((sel >> 1) * 8);
    uint32_t bRow[4] = { (uint32_t)(nB * 128), (uint32_t)((nB + 16) * 128),
                         (uint32_t)((nB + 32) * 128), (uint32_t)((nB + 48) * 128) };
    uint32_t bKb = (uint32_t)((sel & 1) * 16);
    uint32_t bX  = (uint32_t)((nB & 7) << 4);

    int tile = blockIdx.x;
    if (tile >= ntiles) return;

    const char *AbC, *BbC;
    int bxC, byC;
    tile_bases(tile, nxblocks, A, Bt, AbC, BbC, bxC, byC);

    // f16 accumulators: 2 m-frags x 8 n-tiles x 2 packed half2 regs = 32 regs
    uint32_t hacc[2][8][2];
#pragma unroll
    for (int i = 0; i < 2; i++)
#pragma unroll
        for (int j = 0; j < 8; j++) { hacc[i][j][0] = 0u; hacc[i][j][1] = 0u; }

    // prime 2 stages with chunks 0,1 of first tile
    load_chunk(a_sm[0], b_sm[0], AbC, BbC, 0, t); cp_commit();
    load_chunk(a_sm[1], b_sm[1], AbC, BbC, 1, t); cp_commit();

    int stage = 0;
    for (;;) {
        int nxt = tile + gridDim.x;
        bool have_next = nxt < ntiles;
        const char *AbN = nullptr, *BbN = nullptr;
        int bxN, byN;
        if (have_next)
            tile_bases(nxt, nxblocks, A, Bt, AbN, BbN, bxN, byN);

        // output addressing for current tile
        size_t row0 = (size_t)byC * MT;
        int col0 = bxC * NT;
        int tgt = col0 >> 10;
        int colc = col0 & 1023;
        __half* D = (tgt == 0) ? D0 : ((tgt == 1) ? D1 : D2);

#pragma unroll 1
        for (int c = 0; c < NCHUNKS; c++) {
            if (!have_next && c >= NCHUNKS - 2) {
                asm volatile("cp.async.wait_group 0;" ::: "memory");
            } else {
                asm volatile("cp.async.wait_group 1;" ::: "memory");
            }
            __syncthreads();

            int ls = stage + 2; if (ls >= STAGES) ls -= STAGES;
            if (c <= NCHUNKS - 3) {
                load_chunk(a_sm[ls], b_sm[ls], AbC, BbC, c + 2, t);
                cp_commit();
            } else if (have_next) {
                load_chunk(a_sm[ls], b_sm[ls], AbN, BbN, c - (NCHUNKS - 2), t);
                cp_commit();
            }

            uint32_t ab = a_sm[stage], bb = b_sm[stage];
#pragma unroll
            for (int s = 0; s < 4; s++) {         // 4 k16 steps per chunk
                uint32_t kb0 = (uint32_t)(s * 32);
                uint32_t afrag[2][4], bfrag[4][4];
#pragma unroll
                for (int mi = 0; mi < 2; mi++)
                    ldmx4(afrag[mi], ab + aRow[mi] + ((aKb + kb0) ^ aX));
#pragma unroll
                for (int j = 0; j < 4; j++)
                    ldmx4(bfrag[j], bb + bRow[j] + ((bKb + kb0) ^ bX));
#pragma unroll
                for (int mi = 0; mi < 2; mi++)
#pragma unroll
                    for (int j = 0; j < 4; j++) {
                        mma16816h(hacc[mi][2 * j],     afrag[mi], &bfrag[j][0]);
                        mma16816h(hacc[mi][2 * j + 1], afrag[mi], &bfrag[j][2]);
                    }
            }
            stage++; if (stage >= STAGES) stage -= STAGES;
        }

        // Epilogue (runs under next tile's in-flight cp.async loads)
#pragma unroll
        for (int mi = 0; mi < 2; mi++) {
            size_t r0 = row0 + mwarp0 + mi * 16 + (lane >> 2);
#pragma unroll
            for (int nj = 0; nj < 8; nj++) {
                int col = colc + nwarp0 + nj * 8 + (lane & 3) * 2;
                uint32_t v0 = hacc[mi][nj][0];
                uint32_t v1 = hacc[mi][nj][1];
                if (RES) {
                    uint32_t u0 = *(const uint32_t*)(Res + r0 * 1024 + col);
                    uint32_t u1 = *(const uint32_t*)(Res + (r0 + 8) * 1024 + col);
                    __half2 a0 = __hadd2(*(__half2*)&v0, *(__half2*)&u0);
                    __half2 a1 = __hadd2(*(__half2*)&v1, *(__half2*)&u1);
                    v0 = *(uint32_t*)&a0;
                    v1 = *(uint32_t*)&a1;
                }
                *(uint32_t*)(D + r0 * 1024 + col)       = v0;
                *(uint32_t*)(D + (r0 + 8) * 1024 + col) = v1;
                hacc[mi][nj][0] = 0u;
                hacc[mi][nj][1] = 0u;
            }
        }

        if (!have_next) break;
        tile = nxt; AbC = AbN; BbC = BbN; bxC = bxN; byC = byN;
    }
}

// ---------------------------------------------------------------------------
// 3) Attention on tensor cores (f16 in/out, f32 softmax accum).
// ---------------------------------------------------------------------------
#define ATT_WARPS 8
#define ATT_SMEM (ATT_WARPS * 3 * 4096)   // 96 KB
#define ROWSTRIDE_B (LSEQ * NHEAD * DHEAD * 2)  // batch-row stride in bytes

__global__ __launch_bounds__(256) void attn_kernel()
{
    extern __shared__ char asmem[];
    int t = threadIdx.x, w = t >> 5, lane = t & 31;
    uint32_t wbase = smem_to_u32(asmem) + w * 12288;
    uint32_t qsm = wbase, ksm = wbase + 4096, vsm = wbase + 8192;

    int pair = blockIdx.x * ATT_WARPS + w;
    int l = pair >> 4, n = pair & 15;
    size_t ebase = ((size_t)l * NHEAD + n) * DHEAD;
    const char* qg = (const char*)(g_qb + ebase);
    const char* kg = (const char*)(g_kb + ebase);
    const char* vg = (const char*)(g_vb + ebase);

#pragma unroll
    for (int i = 0; i < 8; i++) {
        int s = lane + 32 * i;
        int row = s >> 3, sub = s & 7;
        size_t go = (size_t)row * ROWSTRIDE_B + sub * 16;
        uint32_t so = SMEM_SWIZZLE_128B((uint32_t)(row * 128 + sub * 16));
        cp_async16(qsm + so, qg + go);
        cp_async16(ksm + so, kg + go);
        cp_async16(vsm + so, vg + go);
    }
    cp_commit();
    asm volatile("cp.async.wait_group 0;" ::: "memory");
    __syncwarp();

    int g8 = lane & 7, sel = lane >> 3;

    // ---- S = Q K^T ----
    float c[2][4][4];
#pragma unroll
    for (int mi = 0; mi < 2; mi++)
#pragma unroll
        for (int j = 0; j < 4; j++)
#pragma unroll
            for (int k = 0; k < 4; k++) c[mi][j][k] = 0.f;

#pragma unroll
    for (int kc = 0; kc < 4; kc++) {
        uint32_t kb = kc * 32;
        uint32_t af[2][4], bfr[2][4];
#pragma unroll
        for (int mi = 0; mi < 2; mi++) {
            int row = mi * 16 + g8 + (sel & 1) * 8;
            uint32_t off = row * 128 + ((kb + (sel >> 1) * 16) ^ ((row & 7) << 4));
            ldmx4(af[mi], qsm + off);
        }
#pragma unroll
        for (int nj2 = 0; nj2 < 2; nj2++) {
            int row = nj2 * 16 + g8 + (sel >> 1) * 8;
            uint32_t off = row * 128 + ((kb + (sel & 1) * 16) ^ ((row & 7) << 4));
            ldmx4(bfr[nj2], ksm + off);
        }
#pragma unroll
        for (int mi = 0; mi < 2; mi++)
#pragma unroll
            for (int nj2 = 0; nj2 < 2; nj2++) {
                mma16816f(c[mi][2 * nj2],     af[mi], &bfr[nj2][0]);
                mma16816f(c[mi][2 * nj2 + 1], af[mi], &bfr[nj2][2]);
            }
    }

    // ---- softmax ----
    float inv0[2], inv1[2];
#pragma unroll
    for (int mi = 0; mi < 2; mi++) {
        float m0 = -FLT_MAX, m1 = -FLT_MAX;
#pragma unroll
        for (int j = 0; j < 4; j++) {
#pragma unroll
            for (int k = 0; k < 4; k++) c[mi][j][k] *= 0.125f;
            m0 = fmaxf(m0, fmaxf(c[mi][j][0], c[mi][j][1]));
            m1 = fmaxf(m1, fmaxf(c[mi][j][2], c[mi][j][3]));
        }
        m0 = fmaxf(m0, __shfl_xor_sync(0xffffffffu, m0, 1));
        m0 = fmaxf(m0, __shfl_xor_sync(0xffffffffu, m0, 2));
        m1 = fmaxf(m1, __shfl_xor_sync(0xffffffffu, m1, 1));
        m1 = fmaxf(m1, __shfl_xor_sync(0xffffffffu, m1, 2));
        float s0 = 0.f, s1 = 0.f;
#pragma unroll
        for (int j = 0; j < 4; j++) {
            c[mi][j][0] = __expf(c[mi][j][0] - m0);
            c[mi][j][1] = __expf(c[mi][j][1] - m0);
            c[mi][j][2] = __expf(c[mi][j][2] - m1);
            c[mi][j][3] = __expf(c[mi][j][3] - m1);
            s0 += c[mi][j][0] + c[mi][j][1];
            s1 += c[mi][j][2] + c[mi][j][3];
        }
        s0 += __shfl_xor_sync(0xffffffffu, s0, 1);
        s0 += __shfl_xor_sync(0xffffffffu, s0, 2);
        s1 += __shfl_xor_sync(0xffffffffu, s1, 1);
        s1 += __shfl_xor_sync(0xffffffffu, s1, 2);
        inv0[mi] = 1.f / s0;
        inv1[mi] = 1.f / s1;
    }

    // ---- pack P ----
    uint32_t pf[2][2][4];
#pragma unroll
    for (int mi = 0; mi < 2; mi++)
#pragma unroll
        for (int kc = 0; kc < 2; kc++) {
            __half2 x0 = __floats2half2_rn(c[mi][2 * kc][0],     c[mi][2 * kc][1]);
            __half2 x1 = __floats2half2_rn(c[mi][2 * kc][2],     c[mi][2 * kc][3]);
            __half2 x2 = __floats2half2_rn(c[mi][2 * kc + 1][0], c[mi][2 * kc + 1][1]);
            __half2 x3 = __floats2half2_rn(c[mi][2 * kc + 1][2], c[mi][2 * kc + 1][3]);
            pf[mi][kc][0] = *(uint32_t*)&x0;
            pf[mi][kc][1] = *(uint32_t*)&x1;
            pf[mi][kc][2] = *(uint32_t*)&x2;
            pf[mi][kc][3] = *(uint32_t*)&x3;
        }

    // ---- att = P V ----
    float cv[2][8][4];
#pragma unroll
    for (int mi = 0; mi < 2; mi++)
#pragma unroll
        for (int j = 0; j < 8; j++)
#pragma unroll
            for (int k = 0; k < 4; k++) cv[mi][j][k] = 0.f;

#pragma unroll
    for (int kc = 0; kc < 2; kc++) {
#pragma unroll
        for (int dj2 = 0; dj2 < 4; dj2++) {
            int row = kc * 16 + g8 + (sel & 1) * 8;
            uint32_t colb = dj2 * 32 + (sel >> 1) * 16;
            uint32_t off = row * 128 + (colb ^ ((row & 7) << 4));
            uint32_t bv[4];
            ldmx4t(bv, vsm + off);
#pragma unroll
            for (int mi = 0; mi < 2; mi++) {
                mma16816f(cv[mi][2 * dj2],     pf[mi][kc], &bv[0]);
                mma16816f(cv[mi][2 * dj2 + 1], pf[mi][kc], &bv[2]);
            }
        }
    }

    // ---- normalize + store ----
    int r = lane >> 2, cq = (lane & 3) * 2;
#pragma unroll
    for (int mi = 0; mi < 2; mi++) {
        int i0 = mi * 16 + r;
        __half* o0 = g_qb + ebase + (size_t)i0 * (LSEQ * NHEAD * DHEAD);
        __half* o1 = o0 + (size_t)8 * (LSEQ * NHEAD * DHEAD);
#pragma unroll
        for (int dj = 0; dj < 8; dj++) {
            int col = dj * 8 + cq;
            __half2 h0 = __floats2half2_rn(cv[mi][dj][0] * inv0[mi],
                                           cv[mi][dj][1] * inv0[mi]);
            __half2 h1 = __floats2half2_rn(cv[mi][dj][2] * inv1[mi],
                                           cv[mi][dj][3] * inv1[mi]);
            *(uint32_t*)(o0 + col) = *(uint32_t*)&h0;
            *(uint32_t*)(o1 + col) = *(uint32_t*)&h1;
        }
    }
}

// ---------------------------------------------------------------------------
// 4) Logits
// ---------------------------------------------------------------------------
__global__ void zero_logits_kernel()
{
    if (threadIdx.x < BATCH * NCLS) g_logits[threadIdx.x] = 0.0;
}

__global__ __launch_bounds__(256) void logits_kernel(const float* __restrict__ Wf)
{
    const int CHUNK = 512;
    int i0 = blockIdx.x * CHUNK;
    int t = threadIdx.x;

    float acc[64];
#pragma unroll
    for (int k = 0; k < 64; k++) acc[k] = 0.f;

    for (int s = 0; s < CHUNK; s += 256) {
        int ii = i0 + s + t;
        float w0 = Wf[(size_t)ii * 2];
        float w1 = Wf[(size_t)ii * 2 + 1];
#pragma unroll
        for (int b = 0; b < 32; b++) {
            float v = __half2float(g_ob[(size_t)b * FLAT + ii]);
            acc[2 * b]     += v * w0;
            acc[2 * b + 1] += v * w1;
        }
    }

#pragma unroll
    for (int k = 0; k < 64; k++) {
        float v = acc[k];
        v += __shfl_down_sync(0xffffffffu, v, 16);
        v += __shfl_down_sync(0xffffffffu, v, 8);
        v += __shfl_down_sync(0xffffffffu, v, 4);
        v += __shfl_down_sync(0xffffffffu, v, 2);
        v += __shfl_down_sync(0xffffffffu, v, 1);
        acc[k] = v;
    }

    __shared__ float sacc[64];
    if (t < 64) sacc[t] = 0.f;
    __syncthreads();
    if ((t & 31) == 0) {
#pragma unroll
        for (int k = 0; k < 64; k++) atomicAdd(&sacc[k], acc[k]);
    }
    __syncthreads();
    if (t < 64) atomicAdd(&g_logits[t], (double)sacc[t]);
}

// ---------------------------------------------------------------------------
// 5) Loss
// ---------------------------------------------------------------------------
__global__ void loss_kernel(const int* __restrict__ y,
                            const float* __restrict__ bf,
                            float* __restrict__ out)
{
    if (threadIdx.x != 0 || blockIdx.x != 0) return;
    double s = 0.0;
    double b0 = (double)bf[0], b1 = (double)bf[1];
    for (int b = 0; b < BATCH; b++) {
        double l0 = g_logits[2 * b]     + b0;
        double l1 = g_logits[2 * b + 1] + b1;
        double m  = l0 > l1 ? l0 : l1;
        double lse = m + log(exp(l0 - m) + exp(l1 - m));
        double lp  = (y[b] == 0 ? l0 : l1) - lse;
        s += lp;
    }
    out[0] = (float)(-s / (double)BATCH);
}

// ---------------------------------------------------------------------------
// Launch
// ---------------------------------------------------------------------------
extern "C" void kernel_launch(void* const* d_in, const int* in_sizes, int n_in,
                              void* d_out, int out_size)
{
    const int*   x     = (const int*)d_in[0];
    const int*   y     = (const int*)d_in[1];
    const float* emb   = (const float*)d_in[2];
    const float* Wq    = (const float*)d_in[3];
    const float* Wkv   = (const float*)d_in[4];
    const float* Wo    = (const float*)d_in[5];
    const float* Wf    = (const float*)d_in[6];
    const float* bf    = (const float*)d_in[7];
    float* out = (float*)d_out;

    __half *p_hb, *p_qb, *p_kb, *p_vb, *p_ob, *p_wqkv, *p_wo;
    cudaGetSymbolAddress((void**)&p_hb,   g_hb);
    cudaGetSymbolAddress((void**)&p_qb,   g_qb);
    cudaGetSymbolAddress((void**)&p_kb,   g_kb);
    cudaGetSymbolAddress((void**)&p_vb,   g_vb);
    cudaGetSymbolAddress((void**)&p_ob,   g_ob);
    cudaGetSymbolAddress((void**)&p_wqkv, g_wqkv);
    cudaGetSymbolAddress((void**)&p_wo,   g_wo);

    cudaFuncSetAttribute(gemm_f16_persist<false>,
                         cudaFuncAttributeMaxDynamicSharedMemorySize, GEMM_SMEM);
    cudaFuncSetAttribute(gemm_f16_persist<true>,
                         cudaFuncAttributeMaxDynamicSharedMemorySize, GEMM_SMEM);
    cudaFuncSetAttribute(attn_kernel,
                         cudaFuncAttributeMaxDynamicSharedMemorySize, ATT_SMEM);

    int nsm = 148;
    cudaDeviceGetAttribute(&nsm, cudaDevAttrMultiProcessorCount, 0);
    int ncta = 2 * nsm;   // 2 CTAs/SM (smem-limited occupancy)

    // 1) gather + fused weight prep
    gather_kernel<<<ROWS, 256>>>(x, emb);
    dim3 tgrid(32, 32, 4), tblk(256);
    transpose_all_kernel<<<tgrid, tblk>>>(Wq, Wkv, Wo, p_wqkv, p_wo);

    // 2) fused QKV projection: persistent GEMM, N = 3072
    {
        int nx = 3 * EDIM / NT;              // 24
        int ntiles = nx * (ROWS / MT);       // 12288
        gemm_f16_persist<false><<<ncta, 256, GEMM_SMEM>>>(
            p_hb, p_wqkv, nullptr, p_qb, p_kb, p_vb, nx, ntiles);
    }

    // 3) attention (tensor cores; in place: g_qb <- att)
    attn_kernel<<<LSEQ * NHEAD / ATT_WARPS, 256, ATT_SMEM>>>();

    // 4) out = h + att @ Wo (persistent GEMM)
    {
        int nx = EDIM / NT;                  // 8
        int ntiles = nx * (ROWS / MT);       // 4096
        gemm_f16_persist<true><<<ncta, 256, GEMM_SMEM>>>(
            p_qb, p_wo, p_hb, p_ob, p_ob, p_ob, nx, ntiles);
    }

    // 5) logits + loss
    zero_logits_kernel<<<1, 64>>>();
    logits_kernel<<<FLAT / 512, 256>>>(Wf);
    loss_kernel<<<1, 32>>>(y, bf, out);
}

// round 11
// speedup vs baseline: 1.0888x; 1.0888x over previous
#include <cuda_runtime.h>
#include <cuda_fp16.h>
#include <math.h>
#include <float.h>
#include <stdint.h>

// Problem constants
#define BATCH 32
#define LSEQ  2048
#define EDIM  1024
#define NHEAD 16
#define DHEAD 64
#define HD    (NHEAD * DHEAD)     // 1024
#define ROWS  (BATCH * LSEQ)      // 65536
#define FLAT  (LSEQ * EDIM)       // 2097152
#define NCLS  2

#define SMEM_SWIZZLE_128B(byte_offset) \
    ((byte_offset) ^ (((byte_offset) >> 3) & 0x70))

__device__ __forceinline__ uint32_t smem_to_u32(const void* smem_ptr) {
    uint32_t addr;
    asm("{ .reg .u64 tmp; cvta.to.shared.u64 tmp, %1; cvt.u32.u64 %0, tmp; }"
        : "=r"(addr) : "l"(smem_ptr));
    return addr;
}

__device__ __forceinline__ void cp_async16(uint32_t smem_addr, const void* gptr) {
    asm volatile("cp.async.cg.shared.global [%0], [%1], 16;"
                 :: "r"(smem_addr), "l"(gptr) : "memory");
}
__device__ __forceinline__ void cp_commit() {
    asm volatile("cp.async.commit_group;" ::: "memory");
}

__device__ __forceinline__ void ldmx4(uint32_t* r, uint32_t addr) {
    asm volatile("ldmatrix.sync.aligned.m8n8.x4.shared.b16 {%0,%1,%2,%3}, [%4];"
                 : "=r"(r[0]), "=r"(r[1]), "=r"(r[2]), "=r"(r[3]) : "r"(addr));
}
__device__ __forceinline__ void ldmx4t(uint32_t* r, uint32_t addr) {
    asm volatile("ldmatrix.sync.aligned.m8n8.x4.trans.shared.b16 {%0,%1,%2,%3}, [%4];"
                 : "=r"(r[0]), "=r"(r[1]), "=r"(r[2]), "=r"(r[3]) : "r"(addr));
}

// f16 inputs, f16 accumulator
__device__ __forceinline__ void mma16816h(uint32_t* c, const uint32_t* a, const uint32_t* b) {
    asm volatile(
        "mma.sync.aligned.m16n8k16.row.col.f16.f16.f16.f16 "
        "{%0,%1}, {%2,%3,%4,%5}, {%6,%7}, {%0,%1};"
        : "+r"(c[0]), "+r"(c[1])
        : "r"(a[0]), "r"(a[1]), "r"(a[2]), "r"(a[3]), "r"(b[0]), "r"(b[1]));
}

// f16 inputs, f32 accumulator (attention)
__device__ __forceinline__ void mma16816f(float* c, const uint32_t* a, const uint32_t* b) {
    asm volatile(
        "mma.sync.aligned.m16n8k16.row.col.f32.f16.f16.f32 "
        "{%0,%1,%2,%3}, {%4,%5,%6,%7}, {%8,%9}, {%0,%1,%2,%3};"
        : "+f"(c[0]), "+f"(c[1]), "+f"(c[2]), "+f"(c[3])
        : "r"(a[0]), "r"(a[1]), "r"(a[2]), "r"(a[3]), "r"(b[0]), "r"(b[1]));
}

// ---------------------------------------------------------------------------
// Device-global scratch (f16)
// ---------------------------------------------------------------------------
__device__ __half g_hb[(size_t)ROWS * EDIM];     // 128 MB
__device__ __half g_qb[(size_t)ROWS * HD];       // q, then att (in place)
__device__ __half g_kb[(size_t)ROWS * HD];
__device__ __half g_vb[(size_t)ROWS * HD];
__device__ __half g_wqkv[(size_t)3 * HD * EDIM]; // fused Wq^T|Wk^T|Wv^T
__device__ __half g_wo[(size_t)EDIM * HD];
__device__ double g_logits[BATCH * NCLS];

// ---------------------------------------------------------------------------
// 1) Embedding gather -> f16
// ---------------------------------------------------------------------------
__global__ __launch_bounds__(256) void gather_kernel(
    const int* __restrict__ x, const float* __restrict__ emb)
{
    int row = blockIdx.x;
    int v = x[row];
    int t = threadIdx.x;
    float4 f = ((const float4*)(emb + (size_t)v * EDIM))[t];
    __half2 lo = __floats2half2_rn(f.x, f.y);
    __half2 hi = __floats2half2_rn(f.z, f.w);
    uint2 p;
    p.x = *(uint32_t*)&lo;
    p.y = *(uint32_t*)&hi;
    ((uint2*)(g_hb + (size_t)row * EDIM))[t] = p;
}

// ---------------------------------------------------------------------------
// 1b) Fused weight transpose + convert (grid.z selects which weight)
// ---------------------------------------------------------------------------
__global__ __launch_bounds__(256) void transpose_all_kernel(
    const float* __restrict__ Wq, const float* __restrict__ Wkv,
    const float* __restrict__ Wo,
    __half* __restrict__ wqkv, __half* __restrict__ wo)
{
    __shared__ float tile[32][33];
    const float* in; int ldin, coloff; __half* out;
    switch (blockIdx.z) {
        case 0: in = Wq;  ldin = HD;     coloff = 0;  out = wqkv;                         break;
        case 1: in = Wkv; ldin = 2 * HD; coloff = 0;  out = wqkv + (size_t)HD * EDIM;     break;
        case 2: in = Wkv; ldin = 2 * HD; coloff = HD; out = wqkv + (size_t)2 * HD * EDIM; break;
        default: in = Wo; ldin = EDIM;   coloff = 0;  out = wo;                           break;
    }
    int bx = blockIdx.x * 32;  // n block
    int by = blockIdx.y * 32;  // k block
    int tx = threadIdx.x & 31;
    int ty = threadIdx.x >> 5;
    for (int i = ty; i < 32; i += 8)
        tile[i][tx] = in[(size_t)(by + i) * ldin + coloff + bx + tx];
    __syncthreads();
    for (int i = ty; i < 32; i += 8)
        out[(size_t)(bx + i) * 1024 + by + tx] = __float2half(tile[tx][i]);
}

// ---------------------------------------------------------------------------
// 2) f16 tensor-core GEMM (R8 structure: 128x128, 256 thr, 3-stage, 2 CTA/SM,
//    HW-scheduled grid + raster swizzle).
//    LOGITS variant: instead of storing D, the epilogue computes
//    sum_i (acc+res)[row,col] * Wf[l*1024+col, c] and atomically adds the
//    per-CTA partial into g_logits[b*2+c]. g_ob never materializes.
// ---------------------------------------------------------------------------
#define MT 128
#define NT 128
#define A_BYTES (MT * 128)          // 16 KB per K-chunk of 64
#define B_BYTES (NT * 128)          // 16 KB
#define NCHUNKS 16
#define STAGES 3
#define GEMM_SMEM (STAGES * (A_BYTES + B_BYTES) + 1024)   // 99328

__device__ __forceinline__ void load_chunk(
    uint32_t abuf, uint32_t bbuf,
    const char* Abase, const char* Bbase, int c, int t)
{
#pragma unroll
    for (int i = 0; i < 4; i++) {
        int seg = t + 256 * i;
        int r = seg >> 3, s = seg & 7;
        uint32_t off = SMEM_SWIZZLE_128B((uint32_t)(r * 128 + s * 16));
        cp_async16(abuf + off, Abase + (size_t)r * 2048 + c * 128 + s * 16);
    }
#pragma unroll
    for (int i = 0; i < 4; i++) {
        int seg = t + 256 * i;
        int r = seg >> 3, s = seg & 7;
        uint32_t off = SMEM_SWIZZLE_128B((uint32_t)(r * 128 + s * 16));
        cp_async16(bbuf + off, Bbase + (size_t)r * 2048 + c * 128 + s * 16);
    }
}

template<bool RES, bool LOGITS>
__global__ __launch_bounds__(256, 2) void gemm_f16_kernel(
    const __half* __restrict__ A,
    const __half* __restrict__ Bt,
    const __half* __restrict__ Res,
    __half* __restrict__ D0,
    __half* __restrict__ D1,
    __half* __restrict__ D2,
    const float* __restrict__ Wf,
    int nxblocks)
{
    extern __shared__ char smem[];
    uint32_t base = (smem_to_u32(smem) + 1023) & ~1023u;
    uint32_t a_sm[STAGES], b_sm[STAGES];
#pragma unroll
    for (int s = 0; s < STAGES; s++) {
        a_sm[s] = base + s * (A_BYTES + B_BYTES);
        b_sm[s] = a_sm[s] + A_BYTES;
    }

    int t = threadIdx.x;
    int wid = t >> 5, lane = t & 31;
    int mwarp0 = (wid & 3) * 32;
    int nwarp0 = (wid >> 2) * 64;

    // Raster swizzle: group 8 y-blocks per x-stripe.
    int bid = blockIdx.x;
    int group = bid / (nxblocks * 8);
    int rem   = bid % (nxblocks * 8);
    int bx = rem % nxblocks;
    int by = group * 8 + (rem / nxblocks);

    size_t row0 = (size_t)by * MT;
    int col0 = bx * NT;

    int tgt = col0 >> 10;
    int colc = col0 & 1023;
    __half* D = (tgt == 0) ? D0 : ((tgt == 1) ? D1 : D2);

    const char* Abase = (const char*)(A + row0 * 1024);
    const char* Bbase = (const char*)(Bt + (size_t)col0 * 1024);

    // per-lane ldmatrix address components
    int g = lane & 7, sel = lane >> 3;
    int mA = mwarp0 + g + (sel & 1) * 8;
    uint32_t aRow[2] = { (uint32_t)(mA * 128), (uint32_t)((mA + 16) * 128) };
    uint32_t aKb = (uint32_t)((sel >> 1) * 16);
    uint32_t aX  = (uint32_t)((mA & 7) << 4);

    int nB = nwarp0 + g + ((sel >> 1) * 8);
    uint32_t bRow[4] = { (uint32_t)(nB * 128), (uint32_t)((nB + 16) * 128),
                         (uint32_t)((nB + 32) * 128), (uint32_t)((nB + 48) * 128) };
    uint32_t bKb = (uint32_t)((sel & 1) * 16);
    uint32_t bX  = (uint32_t)((nB & 7) << 4);

    uint32_t hacc[2][8][2];
#pragma unroll
    for (int i = 0; i < 2; i++)
#pragma unroll
        for (int j = 0; j < 8; j++) { hacc[i][j][0] = 0u; hacc[i][j][1] = 0u; }

    load_chunk(a_sm[0], b_sm[0], Abase, Bbase, 0, t); cp_commit();
    load_chunk(a_sm[1], b_sm[1], Abase, Bbase, 1, t); cp_commit();

    int stage = 0;
    for (int c = 0; c < NCHUNKS; c++) {
        if (c < NCHUNKS - 1) {
            asm volatile("cp.async.wait_group 1;" ::: "memory");
        } else {
            asm volatile("cp.async.wait_group 0;" ::: "memory");
        }
        __syncthreads();
        if (c + 2 < NCHUNKS) {
            int ns = stage + 2; if (ns >= STAGES) ns -= STAGES;
            load_chunk(a_sm[ns], b_sm[ns], Abase, Bbase, c + 2, t);
            cp_commit();
        }

        uint32_t ab = a_sm[stage], bb = b_sm[stage];
#pragma unroll
        for (int s = 0; s < 4; s++) {
            uint32_t kb0 = (uint32_t)(s * 32);
            uint32_t afrag[2][4], bfrag[4][4];
#pragma unroll
            for (int mi = 0; mi < 2; mi++)
                ldmx4(afrag[mi], ab + aRow[mi] + ((aKb + kb0) ^ aX));
#pragma unroll
            for (int j = 0; j < 4; j++)
                ldmx4(bfrag[j], bb + bRow[j] + ((bKb + kb0) ^ bX));
#pragma unroll
            for (int mi = 0; mi < 2; mi++)
#pragma unroll
                for (int j = 0; j < 4; j++) {
                    mma16816h(hacc[mi][2 * j],     afrag[mi], &bfrag[j][0]);
                    mma16816h(hacc[mi][2 * j + 1], afrag[mi], &bfrag[j][2]);
                }
        }
        stage++; if (stage >= STAGES) stage -= STAGES;
    }

    if (!LOGITS) {
        // Standard epilogue: packed half2 stores (+ optional residual)
#pragma unroll
        for (int mi = 0; mi < 2; mi++) {
            size_t r0 = row0 + mwarp0 + mi * 16 + (lane >> 2);
#pragma unroll
            for (int nj = 0; nj < 8; nj++) {
                int col = colc + nwarp0 + nj * 8 + (lane & 3) * 2;
                uint32_t v0 = hacc[mi][nj][0];
                uint32_t v1 = hacc[mi][nj][1];
                if (RES) {
                    uint32_t u0 = *(const uint32_t*)(Res + r0 * 1024 + col);
                    uint32_t u1 = *(const uint32_t*)(Res + (r0 + 8) * 1024 + col);
                    __half2 a0 = __hadd2(*(__half2*)&v0, *(__half2*)&u0);
                    __half2 a1 = __hadd2(*(__half2*)&v1, *(__half2*)&u1);
                    v0 = *(uint32_t*)&a0;
                    v1 = *(uint32_t*)&a1;
                }
                *(uint32_t*)(D + r0 * 1024 + col)       = v0;
                *(uint32_t*)(D + (r0 + 8) * 1024 + col) = v1;
            }
        }
    } else {
        // Fused-logits epilogue: out = acc + res (f32); dot with Wf; reduce.
        float a0 = 0.f, a1 = 0.f;
        int bidx = (int)(row0 >> 11);   // 2048 rows per batch; tile within 1 b
#pragma unroll
        for (int mi = 0; mi < 2; mi++) {
            size_t r0 = row0 + mwarp0 + mi * 16 + (lane >> 2);
            int l0 = (int)(r0 & 2047);
#pragma unroll
            for (int nj = 0; nj < 8; nj++) {
                int col = colc + nwarp0 + nj * 8 + (lane & 3) * 2;
                uint32_t v0 = hacc[mi][nj][0];
                uint32_t v1 = hacc[mi][nj][1];
                uint32_t u0 = *(const uint32_t*)(Res + r0 * 1024 + col);
                uint32_t u1 = *(const uint32_t*)(Res + (r0 + 8) * 1024 + col);
                __half2 s0 = __hadd2(*(__half2*)&v0, *(__half2*)&u0);
                __half2 s1 = __hadd2(*(__half2*)&v1, *(__half2*)&u1);
                float2 f0 = __half22float2(s0);
                float2 f1 = __half22float2(s1);
                // Wf rows are [flat, 2]; float4 covers (flat, flat+1) x 2 cls
                const float4 w0 = *(const float4*)(Wf + ((size_t)l0 * 1024 + col) * 2);
                const float4 w1 = *(const float4*)(Wf + ((size_t)(l0 + 8) * 1024 + col) * 2);
                a0 += f0.x * w0.x + f0.y * w0.z + f1.x * w1.x + f1.y * w1.z;
                a1 += f0.x * w0.y + f0.y * w0.w + f1.x * w1.y + f1.y * w1.w;
            }
        }
        // warp reduce
#pragma unroll
        for (int off = 16; off >= 1; off >>= 1) {
            a0 += __shfl_xor_sync(0xffffffffu, a0, off);
            a1 += __shfl_xor_sync(0xffffffffu, a1, off);
        }
        __shared__ float red[8][2];
        if (lane == 0) { red[wid][0] = a0; red[wid][1] = a1; }
        __syncthreads();
        if (t == 0) {
            float s0 = 0.f, s1 = 0.f;
#pragma unroll
            for (int wv = 0; wv < 8; wv++) { s0 += red[wv][0]; s1 += red[wv][1]; }
            atomicAdd(&g_logits[2 * bidx],     (double)s0);
            atomicAdd(&g_logits[2 * bidx + 1], (double)s1);
        }
    }
}

// ---------------------------------------------------------------------------
// 3) Attention on tensor cores (f16 in/out, f32 softmax accum).
// ---------------------------------------------------------------------------
#define ATT_WARPS 8
#define ATT_SMEM (ATT_WARPS * 3 * 4096)   // 96 KB
#define ROWSTRIDE_B (LSEQ * NHEAD * DHEAD * 2)  // batch-row stride in bytes

__global__ __launch_bounds__(256) void attn_kernel()
{
    extern __shared__ char asmem[];
    int t = threadIdx.x, w = t >> 5, lane = t & 31;
    uint32_t wbase = smem_to_u32(asmem) + w * 12288;
    uint32_t qsm = wbase, ksm = wbase + 4096, vsm = wbase + 8192;

    int pair = blockIdx.x * ATT_WARPS + w;
    int l = pair >> 4, n = pair & 15;
    size_t ebase = ((size_t)l * NHEAD + n) * DHEAD;
    const char* qg = (const char*)(g_qb + ebase);
    const char* kg = (const char*)(g_kb + ebase);
    const char* vg = (const char*)(g_vb + ebase);

#pragma unroll
    for (int i = 0; i < 8; i++) {
        int s = lane + 32 * i;
        int row = s >> 3, sub = s & 7;
        size_t go = (size_t)row * ROWSTRIDE_B + sub * 16;
        uint32_t so = SMEM_SWIZZLE_128B((uint32_t)(row * 128 + sub * 16));
        cp_async16(qsm + so, qg + go);
        cp_async16(ksm + so, kg + go);
        cp_async16(vsm + so, vg + go);
    }
    cp_commit();
    asm volatile("cp.async.wait_group 0;" ::: "memory");
    __syncwarp();

    int g8 = lane & 7, sel = lane >> 3;

    // ---- S = Q K^T ----
    float c[2][4][4];
#pragma unroll
    for (int mi = 0; mi < 2; mi++)
#pragma unroll
        for (int j = 0; j < 4; j++)
#pragma unroll
            for (int k = 0; k < 4; k++) c[mi][j][k] = 0.f;

#pragma unroll
    for (int kc = 0; kc < 4; kc++) {
        uint32_t kb = kc * 32;
        uint32_t af[2][4], bfr[2][4];
#pragma unroll
        for (int mi = 0; mi < 2; mi++) {
            int row = mi * 16 + g8 + (sel & 1) * 8;
            uint32_t off = row * 128 + ((kb + (sel >> 1) * 16) ^ ((row & 7) << 4));
            ldmx4(af[mi], qsm + off);
        }
#pragma unroll
        for (int nj2 = 0; nj2 < 2; nj2++) {
            int row = nj2 * 16 + g8 + (sel >> 1) * 8;
            uint32_t off = row * 128 + ((kb + (sel & 1) * 16) ^ ((row & 7) << 4));
            ldmx4(bfr[nj2], ksm + off);
        }
#pragma unroll
        for (int mi = 0; mi < 2; mi++)
#pragma unroll
            for (int nj2 = 0; nj2 < 2; nj2++) {
                mma16816f(c[mi][2 * nj2],     af[mi], &bfr[nj2][0]);
                mma16816f(c[mi][2 * nj2 + 1], af[mi], &bfr[nj2][2]);
            }
    }

    // ---- softmax ----
    float inv0[2], inv1[2];
#pragma unroll
    for (int mi = 0; mi < 2; mi++) {
        float m0 = -FLT_MAX, m1 = -FLT_MAX;
#pragma unroll
        for (int j = 0; j < 4; j++) {
#pragma unroll
            for (int k = 0; k < 4; k++) c[mi][j][k] *= 0.125f;
            m0 = fmaxf(m0, fmaxf(c[mi][j][0], c[mi][j][1]));
            m1 = fmaxf(m1, fmaxf(c[mi][j][2], c[mi][j][3]));
        }
        m0 = fmaxf(m0, __shfl_xor_sync(0xffffffffu, m0, 1));
        m0 = fmaxf(m0, __shfl_xor_sync(0xffffffffu, m0, 2));
        m1 = fmaxf(m1, __shfl_xor_sync(0xffffffffu, m1, 1));
        m1 = fmaxf(m1, __shfl_xor_sync(0xffffffffu, m1, 2));
        float s0 = 0.f, s1 = 0.f;
#pragma unroll
        for (int j = 0; j < 4; j++) {
            c[mi][j][0] = __expf(c[mi][j][0] - m0);
            c[mi][j][1] = __expf(c[mi][j][1] - m0);
            c[mi][j][2] = __expf(c[mi][j][2] - m1);
            c[mi][j][3] = __expf(c[mi][j][3] - m1);
            s0 += c[mi][j][0] + c[mi][j][1];
            s1 += c[mi][j][2] + c[mi][j][3];
        }
        s0 += __shfl_xor_sync(0xffffffffu, s0, 1);
        s0 += __shfl_xor_sync(0xffffffffu, s0, 2);
        s1 += __shfl_xor_sync(0xffffffffu, s1, 1);
        s1 += __shfl_xor_sync(0xffffffffu, s1, 2);
        inv0[mi] = 1.f / s0;
        inv1[mi] = 1.f / s1;
    }

    // ---- pack P ----
    uint32_t pf[2][2][4];
#pragma unroll
    for (int mi = 0; mi < 2; mi++)
#pragma unroll
        for (int kc = 0; kc < 2; kc++) {
            __half2 x0 = __floats2half2_rn(c[mi][2 * kc][0],     c[mi][2 * kc][1]);
            __half2 x1 = __floats2half2_rn(c[mi][2 * kc][2],     c[mi][2 * kc][3]);
            __half2 x2 = __floats2half2_rn(c[mi][2 * kc + 1][0], c[mi][2 * kc + 1][1]);
            __half2 x3 = __floats2half2_rn(c[mi][2 * kc + 1][2], c[mi][2 * kc + 1][3]);
            pf[mi][kc][0] = *(uint32_t*)&x0;
            pf[mi][kc][1] = *(uint32_t*)&x1;
            pf[mi][kc][2] = *(uint32_t*)&x2;
            pf[mi][kc][3] = *(uint32_t*)&x3;
        }

    // ---- att = P V ----
    float cv[2][8][4];
#pragma unroll
    for (int mi = 0; mi < 2; mi++)
#pragma unroll
        for (int j = 0; j < 8; j++)
#pragma unroll
            for (int k = 0; k < 4; k++) cv[mi][j][k] = 0.f;

#pragma unroll
    for (int kc = 0; kc < 2; kc++) {
#pragma unroll
        for (int dj2 = 0; dj2 < 4; dj2++) {
            int row = kc * 16 + g8 + (sel & 1) * 8;
            uint32_t colb = dj2 * 32 + (sel >> 1) * 16;
            uint32_t off = row * 128 + (colb ^ ((row & 7) << 4));
            uint32_t bv[4];
            ldmx4t(bv, vsm + off);
#pragma unroll
            for (int mi = 0; mi < 2; mi++) {
                mma16816f(cv[mi][2 * dj2],     pf[mi][kc], &bv[0]);
                mma16816f(cv[mi][2 * dj2 + 1], pf[mi][kc], &bv[2]);
            }
        }
    }

    // ---- normalize + store ----
    int r = lane >> 2, cq = (lane & 3) * 2;
#pragma unroll
    for (int mi = 0; mi < 2; mi++) {
        int i0 = mi * 16 + r;
        __half* o0 = g_qb + ebase + (size_t)i0 * (LSEQ * NHEAD * DHEAD);
        __half* o1 = o0 + (size_t)8 * (LSEQ * NHEAD * DHEAD);
#pragma unroll
        for (int dj = 0; dj < 8; dj++) {
            int col = dj * 8 + cq;
            __half2 h0 = __floats2half2_rn(cv[mi][dj][0] * inv0[mi],
                                           cv[mi][dj][1] * inv0[mi]);
            __half2 h1 = __floats2half2_rn(cv[mi][dj][2] * inv1[mi],
                                           cv[mi][dj][3] * inv1[mi]);
            *(uint32_t*)(o0 + col) = *(uint32_t*)&h0;
            *(uint32_t*)(o1 + col) = *(uint32_t*)&h1;
        }
    }
}

// ---------------------------------------------------------------------------
// 4) Logit zero + loss
// ---------------------------------------------------------------------------
__global__ void zero_logits_kernel()
{
    if (threadIdx.x < BATCH * NCLS) g_logits[threadIdx.x] = 0.0;
}

__global__ void loss_kernel(const int* __restrict__ y,
                            const float* __restrict__ bf,
                            float* __restrict__ out)
{
    if (threadIdx.x != 0 || blockIdx.x != 0) return;
    double s = 0.0;
    double b0 = (double)bf[0], b1 = (double)bf[1];
    for (int b = 0; b < BATCH; b++) {
        double l0 = g_logits[2 * b]     + b0;
        double l1 = g_logits[2 * b + 1] + b1;
        double m  = l0 > l1 ? l0 : l1;
        double lse = m + log(exp(l0 - m) + exp(l1 - m));
        double lp  = (y[b] == 0 ? l0 : l1) - lse;
        s += lp;
    }
    out[0] = (float)(-s / (double)BATCH);
}

// ---------------------------------------------------------------------------
// Launch
// ---------------------------------------------------------------------------
extern "C" void kernel_launch(void* const* d_in, const int* in_sizes, int n_in,
                              void* d_out, int out_size)
{
    const int*   x     = (const int*)d_in[0];
    const int*   y     = (const int*)d_in[1];
    const float* emb   = (const float*)d_in[2];
    const float* Wq    = (const float*)d_in[3];
    const float* Wkv   = (const float*)d_in[4];
    const float* Wo    = (const float*)d_in[5];
    const float* Wf    = (const float*)d_in[6];
    const float* bf    = (const float*)d_in[7];
    float* out = (float*)d_out;

    __half *p_hb, *p_qb, *p_kb, *p_vb, *p_wqkv, *p_wo;
    cudaGetSymbolAddress((void**)&p_hb,   g_hb);
    cudaGetSymbolAddress((void**)&p_qb,   g_qb);
    cudaGetSymbolAddress((void**)&p_kb,   g_kb);
    cudaGetSymbolAddress((void**)&p_vb,   g_vb);
    cudaGetSymbolAddress((void**)&p_wqkv, g_wqkv);
    cudaGetSymbolAddress((void**)&p_wo,   g_wo);

    cudaFuncSetAttribute((void*)gemm_f16_kernel<false, false>,
                         cudaFuncAttributeMaxDynamicSharedMemorySize, GEMM_SMEM);
    cudaFuncSetAttribute((void*)gemm_f16_kernel<true, true>,
                         cudaFuncAttributeMaxDynamicSharedMemorySize, GEMM_SMEM);
    cudaFuncSetAttribute(attn_kernel,
                         cudaFuncAttributeMaxDynamicSharedMemorySize, ATT_SMEM);

    // 1) gather + fused weight prep
    gather_kernel<<<ROWS, 256>>>(x, emb);
    dim3 tgrid(32, 32, 4), tblk(256);
    transpose_all_kernel<<<tgrid, tblk>>>(Wq, Wkv, Wo, p_wqkv, p_wo);

    // 2) fused QKV projection: one GEMM, N = 3072
    {
        int nx = 3 * EDIM / NT;              // 24
        gemm_f16_kernel<false, false><<<dim3(nx * (ROWS / MT), 1), 256, GEMM_SMEM>>>(
            p_hb, p_wqkv, nullptr, p_qb, p_kb, p_vb, nullptr, nx);
    }

    // 3) attention (tensor cores; in place: g_qb <- att)
    attn_kernel<<<LSEQ * NHEAD / ATT_WARPS, 256, ATT_SMEM>>>();

    // 4) out = h + att @ Wo, fused with logits = out . Wf  (no g_ob)
    zero_logits_kernel<<<1, 64>>>();
    {
        int nx = EDIM / NT;                  // 8
        gemm_f16_kernel<true, true><<<dim3(nx * (ROWS / MT), 1), 256, GEMM_SMEM>>>(
            p_qb, p_wo, p_hb, nullptr, nullptr, nullptr, Wf, nx);
    }

    // 5) loss
    loss_kernel<<<1, 32>>>(y, bf, out);
}

// round 12
// speedup vs baseline: 1.2535x; 1.1512x over previous
#include <cuda_runtime.h>
#include <cuda_fp16.h>
#include <math.h>
#include <float.h>
#include <stdint.h>

// Problem constants
#define BATCH 32
#define LSEQ  2048
#define EDIM  1024
#define NHEAD 16
#define DHEAD 64
#define HD    (NHEAD * DHEAD)     // 1024
#define ROWS  (BATCH * LSEQ)      // 65536
#define FLAT  (LSEQ * EDIM)       // 2097152
#define NCLS  2

#define SMEM_SWIZZLE_128B(byte_offset) \
    ((byte_offset) ^ (((byte_offset) >> 3) & 0x70))

__device__ __forceinline__ uint32_t smem_to_u32(const void* smem_ptr) {
    uint32_t addr;
    asm("{ .reg .u64 tmp; cvta.to.shared.u64 tmp, %1; cvt.u32.u64 %0, tmp; }"
        : "=r"(addr) : "l"(smem_ptr));
    return addr;
}

__device__ __forceinline__ void cp_async16(uint32_t smem_addr, const void* gptr) {
    asm volatile("cp.async.cg.shared.global [%0], [%1], 16;"
                 :: "r"(smem_addr), "l"(gptr) : "memory");
}
__device__ __forceinline__ void cp_commit() {
    asm volatile("cp.async.commit_group;" ::: "memory");
}

__device__ __forceinline__ void ldmx4(uint32_t* r, uint32_t addr) {
    asm volatile("ldmatrix.sync.aligned.m8n8.x4.shared.b16 {%0,%1,%2,%3}, [%4];"
                 : "=r"(r[0]), "=r"(r[1]), "=r"(r[2]), "=r"(r[3]) : "r"(addr));
}
__device__ __forceinline__ void ldmx4t(uint32_t* r, uint32_t addr) {
    asm volatile("ldmatrix.sync.aligned.m8n8.x4.trans.shared.b16 {%0,%1,%2,%3}, [%4];"
                 : "=r"(r[0]), "=r"(r[1]), "=r"(r[2]), "=r"(r[3]) : "r"(addr));
}

// f16 inputs, f16 accumulator
__device__ __forceinline__ void mma16816h(uint32_t* c, const uint32_t* a, const uint32_t* b) {
    asm volatile(
        "mma.sync.aligned.m16n8k16.row.col.f16.f16.f16.f16 "
        "{%0,%1}, {%2,%3,%4,%5}, {%6,%7}, {%0,%1};"
        : "+r"(c[0]), "+r"(c[1])
        : "r"(a[0]), "r"(a[1]), "r"(a[2]), "r"(a[3]), "r"(b[0]), "r"(b[1]));
}

// f16 inputs, f32 accumulator (attention)
__device__ __forceinline__ void mma16816f(float* c, const uint32_t* a, const uint32_t* b) {
    asm volatile(
        "mma.sync.aligned.m16n8k16.row.col.f32.f16.f16.f32 "
        "{%0,%1,%2,%3}, {%4,%5,%6,%7}, {%8,%9}, {%0,%1,%2,%3};"
        : "+f"(c[0]), "+f"(c[1]), "+f"(c[2]), "+f"(c[3])
        : "r"(a[0]), "r"(a[1]), "r"(a[2]), "r"(a[3]), "r"(b[0]), "r"(b[1]));
}

// ---------------------------------------------------------------------------
// Device-global scratch (f16)
// ---------------------------------------------------------------------------
__device__ __half g_hb[(size_t)ROWS * EDIM];     // 128 MB
__device__ __half g_qb[(size_t)ROWS * HD];       // q, then att (in place)
__device__ __half g_kb[(size_t)ROWS * HD];
__device__ __half g_vb[(size_t)ROWS * HD];
__device__ __half g_wqkv[(size_t)3 * HD * EDIM]; // fused Wq^T|Wk^T|Wv^T
__device__ __half g_wo[(size_t)EDIM * HD];
__device__ double g_logits[BATCH * NCLS];

// ---------------------------------------------------------------------------
// 1) Embedding gather -> f16
// ---------------------------------------------------------------------------
__global__ __launch_bounds__(256) void gather_kernel(
    const int* __restrict__ x, const float* __restrict__ emb)
{
    int row = blockIdx.x;
    int v = x[row];
    int t = threadIdx.x;
    float4 f = ((const float4*)(emb + (size_t)v * EDIM))[t];
    __half2 lo = __floats2half2_rn(f.x, f.y);
    __half2 hi = __floats2half2_rn(f.z, f.w);
    uint2 p;
    p.x = *(uint32_t*)&lo;
    p.y = *(uint32_t*)&hi;
    ((uint2*)(g_hb + (size_t)row * EDIM))[t] = p;
}

// ---------------------------------------------------------------------------
// 1b) Fused weight transpose + convert (grid.z selects which weight).
//     Also zeroes g_logits (one block) so no separate launch is needed.
// ---------------------------------------------------------------------------
__global__ __launch_bounds__(256) void transpose_all_kernel(
    const float* __restrict__ Wq, const float* __restrict__ Wkv,
    const float* __restrict__ Wo,
    __half* __restrict__ wqkv, __half* __restrict__ wo)
{
    if (blockIdx.z == 3 && blockIdx.x == 0 && blockIdx.y == 0 &&
        threadIdx.x < BATCH * NCLS)
        g_logits[threadIdx.x] = 0.0;

    __shared__ float tile[32][33];
    const float* in; int ldin, coloff; __half* out;
    switch (blockIdx.z) {
        case 0: in = Wq;  ldin = HD;     coloff = 0;  out = wqkv;                         break;
        case 1: in = Wkv; ldin = 2 * HD; coloff = 0;  out = wqkv + (size_t)HD * EDIM;     break;
        case 2: in = Wkv; ldin = 2 * HD; coloff = HD; out = wqkv + (size_t)2 * HD * EDIM; break;
        default: in = Wo; ldin = EDIM;   coloff = 0;  out = wo;                           break;
    }
    int bx = blockIdx.x * 32;  // n block
    int by = blockIdx.y * 32;  // k block
    int tx = threadIdx.x & 31;
    int ty = threadIdx.x >> 5;
    for (int i = ty; i < 32; i += 8)
        tile[i][tx] = in[(size_t)(by + i) * ldin + coloff + bx + tx];
    __syncthreads();
    for (int i = ty; i < 32; i += 8)
        out[(size_t)(bx + i) * 1024 + by + tx] = __float2half(tile[tx][i]);
}

// ---------------------------------------------------------------------------
// 2) f16 tensor-core GEMM (128x128, 256 thr, 3-stage, 2 CTA/SM).
//    LOGITS variant: epilogue dots (acc+res) with Wf -> g_logits atomics.
//    Raster: GEMM1 groups 8 y-blocks per x-stripe (B reuse). GEMM2/LOGITS
//    orders tiles (lblk, bx, b) with b innermost so the 32 batch-tiles that
//    share one Wf slice run in the same wave (Wf read from DRAM once).
// ---------------------------------------------------------------------------
#define MT 128
#define NT 128
#define A_BYTES (MT * 128)          // 16 KB per K-chunk of 64
#define B_BYTES (NT * 128)          // 16 KB
#define NCHUNKS 16
#define STAGES 3
#define GEMM_SMEM (STAGES * (A_BYTES + B_BYTES) + 1024)   // 99328

__device__ __forceinline__ void load_chunk(
    uint32_t abuf, uint32_t bbuf,
    const char* Abase, const char* Bbase, int c, int t)
{
#pragma unroll
    for (int i = 0; i < 4; i++) {
        int seg = t + 256 * i;
        int r = seg >> 3, s = seg & 7;
        uint32_t off = SMEM_SWIZZLE_128B((uint32_t)(r * 128 + s * 16));
        cp_async16(abuf + off, Abase + (size_t)r * 2048 + c * 128 + s * 16);
    }
#pragma unroll
    for (int i = 0; i < 4; i++) {
        int seg = t + 256 * i;
        int r = seg >> 3, s = seg & 7;
        uint32_t off = SMEM_SWIZZLE_128B((uint32_t)(r * 128 + s * 16));
        cp_async16(bbuf + off, Bbase + (size_t)r * 2048 + c * 128 + s * 16);
    }
}

template<bool RES, bool LOGITS>
__global__ __launch_bounds__(256, 2) void gemm_f16_kernel(
    const __half* __restrict__ A,
    const __half* __restrict__ Bt,
    const __half* __restrict__ Res,
    __half* __restrict__ D0,
    __half* __restrict__ D1,
    __half* __restrict__ D2,
    const float* __restrict__ Wf,
    int nxblocks)
{
    extern __shared__ char smem[];
    uint32_t base = (smem_to_u32(smem) + 1023) & ~1023u;
    uint32_t a_sm[STAGES], b_sm[STAGES];
#pragma unroll
    for (int s = 0; s < STAGES; s++) {
        a_sm[s] = base + s * (A_BYTES + B_BYTES);
        b_sm[s] = a_sm[s] + A_BYTES;
    }

    int t = threadIdx.x;
    int wid = t >> 5, lane = t & 31;
    int mwarp0 = (wid & 3) * 32;
    int nwarp0 = (wid >> 2) * 64;

    int bid = blockIdx.x;
    int bx, by;
    if (LOGITS) {
        // nxblocks == 8; order (lblk, bx, b), b innermost -> Wf slice reuse
        int b    = bid & 31;
        bx       = (bid >> 5) & 7;
        int lblk = bid >> 8;            // 0..15
        by = b * 16 + lblk;
    } else {
        int group = bid / (nxblocks * 8);
        int rem   = bid % (nxblocks * 8);
        bx = rem % nxblocks;
        by = group * 8 + (rem / nxblocks);
    }

    size_t row0 = (size_t)by * MT;
    int col0 = bx * NT;

    int tgt = col0 >> 10;
    int colc = col0 & 1023;
    __half* D = (tgt == 0) ? D0 : ((tgt == 1) ? D1 : D2);

    const char* Abase = (const char*)(A + row0 * 1024);
    const char* Bbase = (const char*)(Bt + (size_t)col0 * 1024);

    // per-lane ldmatrix address components
    int g = lane & 7, sel = lane >> 3;
    int mA = mwarp0 + g + (sel & 1) * 8;
    uint32_t aRow[2] = { (uint32_t)(mA * 128), (uint32_t)((mA + 16) * 128) };
    uint32_t aKb = (uint32_t)((sel >> 1) * 16);
    uint32_t aX  = (uint32_t)((mA & 7) << 4);

    int nB = nwarp0 + g + ((sel >> 1) * 8);
    uint32_t bRow[4] = { (uint32_t)(nB * 128), (uint32_t)((nB + 16) * 128),
                         (uint32_t)((nB + 32) * 128), (uint32_t)((nB + 48) * 128) };
    uint32_t bKb = (uint32_t)((sel & 1) * 16);
    uint32_t bX  = (uint32_t)((nB & 7) << 4);

    uint32_t hacc[2][8][2];
#pragma unroll
    for (int i = 0; i < 2; i++)
#pragma unroll
        for (int j = 0; j < 8; j++) { hacc[i][j][0] = 0u; hacc[i][j][1] = 0u; }

    load_chunk(a_sm[0], b_sm[0], Abase, Bbase, 0, t); cp_commit();
    load_chunk(a_sm[1], b_sm[1], Abase, Bbase, 1, t); cp_commit();

#pragma unroll
    for (int c = 0; c < NCHUNKS; c++) {
        int stage = c % STAGES;
        if (c < NCHUNKS - 1) {
            asm volatile("cp.async.wait_group 1;" ::: "memory");
        } else {
            asm volatile("cp.async.wait_group 0;" ::: "memory");
        }
        __syncthreads();
        if (c + 2 < NCHUNKS) {
            int ns = (c + 2) % STAGES;
            load_chunk(a_sm[ns], b_sm[ns], Abase, Bbase, c + 2, t);
            cp_commit();
        }

        uint32_t ab = a_sm[stage], bb = b_sm[stage];
#pragma unroll
        for (int s = 0; s < 4; s++) {
            uint32_t kb0 = (uint32_t)(s * 32);
            uint32_t afrag[2][4], bfrag[4][4];
#pragma unroll
            for (int mi = 0; mi < 2; mi++)
                ldmx4(afrag[mi], ab + aRow[mi] + ((aKb + kb0) ^ aX));
#pragma unroll
            for (int j = 0; j < 4; j++)
                ldmx4(bfrag[j], bb + bRow[j] + ((bKb + kb0) ^ bX));
#pragma unroll
            for (int mi = 0; mi < 2; mi++)
#pragma unroll
                for (int j = 0; j < 4; j++) {
                    mma16816h(hacc[mi][2 * j],     afrag[mi], &bfrag[j][0]);
                    mma16816h(hacc[mi][2 * j + 1], afrag[mi], &bfrag[j][2]);
                }
        }
    }

    if (!LOGITS) {
        // Standard epilogue: packed half2 stores (+ optional residual)
#pragma unroll
        for (int mi = 0; mi < 2; mi++) {
            size_t r0 = row0 + mwarp0 + mi * 16 + (lane >> 2);
#pragma unroll
            for (int nj = 0; nj < 8; nj++) {
                int col = colc + nwarp0 + nj * 8 + (lane & 3) * 2;
                uint32_t v0 = hacc[mi][nj][0];
                uint32_t v1 = hacc[mi][nj][1];
                if (RES) {
                    uint32_t u0 = *(const uint32_t*)(Res + r0 * 1024 + col);
                    uint32_t u1 = *(const uint32_t*)(Res + (r0 + 8) * 1024 + col);
                    __half2 a0 = __hadd2(*(__half2*)&v0, *(__half2*)&u0);
                    __half2 a1 = __hadd2(*(__half2*)&v1, *(__half2*)&u1);
                    v0 = *(uint32_t*)&a0;
                    v1 = *(uint32_t*)&a1;
                }
                *(uint32_t*)(D + r0 * 1024 + col)       = v0;
                *(uint32_t*)(D + (r0 + 8) * 1024 + col) = v1;
            }
        }
    } else {
        // Fused-logits epilogue: out = acc + res (f32); dot with Wf; reduce.
        float a0 = 0.f, a1 = 0.f;
        int bidx = (int)(row0 >> 11);   // 2048 rows per batch
#pragma unroll
        for (int mi = 0; mi < 2; mi++) {
            size_t r0 = row0 + mwarp0 + mi * 16 + (lane >> 2);
            int l0 = (int)(r0 & 2047);
#pragma unroll
            for (int nj = 0; nj < 8; nj++) {
                int col = colc + nwarp0 + nj * 8 + (lane & 3) * 2;
                uint32_t v0 = hacc[mi][nj][0];
                uint32_t v1 = hacc[mi][nj][1];
                uint32_t u0 = *(const uint32_t*)(Res + r0 * 1024 + col);
                uint32_t u1 = *(const uint32_t*)(Res + (r0 + 8) * 1024 + col);
                __half2 s0 = __hadd2(*(__half2*)&v0, *(__half2*)&u0);
                __half2 s1 = __hadd2(*(__half2*)&v1, *(__half2*)&u1);
                float2 f0 = __half22float2(s0);
                float2 f1 = __half22float2(s1);
                const float4 w0 = *(const float4*)(Wf + ((size_t)l0 * 1024 + col) * 2);
                const float4 w1 = *(const float4*)(Wf + ((size_t)(l0 + 8) * 1024 + col) * 2);
                a0 += f0.x * w0.x + f0.y * w0.z + f1.x * w1.x + f1.y * w1.z;
                a1 += f0.x * w0.y + f0.y * w0.w + f1.x * w1.y + f1.y * w1.w;
            }
        }
#pragma unroll
        for (int off = 16; off >= 1; off >>= 1) {
            a0 += __shfl_xor_sync(0xffffffffu, a0, off);
            a1 += __shfl_xor_sync(0xffffffffu, a1, off);
        }
        __shared__ float red[8][2];
        if (lane == 0) { red[wid][0] = a0; red[wid][1] = a1; }
        __syncthreads();
        if (t == 0) {
            float s0 = 0.f, s1 = 0.f;
#pragma unroll
            for (int wv = 0; wv < 8; wv++) { s0 += red[wv][0]; s1 += red[wv][1]; }
            atomicAdd(&g_logits[2 * bidx],     (double)s0);
            atomicAdd(&g_logits[2 * bidx + 1], (double)s1);
        }
    }
}

// ---------------------------------------------------------------------------
// 3) Attention on tensor cores (f16 in/out, f32 softmax accum).
// ---------------------------------------------------------------------------
#define ATT_WARPS 8
#define ATT_SMEM (ATT_WARPS * 3 * 4096)   // 96 KB
#define ROWSTRIDE_B (LSEQ * NHEAD * DHEAD * 2)  // batch-row stride in bytes

__global__ __launch_bounds__(256) void attn_kernel()
{
    extern __shared__ char asmem[];
    int t = threadIdx.x, w = t >> 5, lane = t & 31;
    uint32_t wbase = smem_to_u32(asmem) + w * 12288;
    uint32_t qsm = wbase, ksm = wbase + 4096, vsm = wbase + 8192;

    int pair = blockIdx.x * ATT_WARPS + w;
    int l = pair >> 4, n = pair & 15;
    size_t ebase = ((size_t)l * NHEAD + n) * DHEAD;
    const char* qg = (const char*)(g_qb + ebase);
    const char* kg = (const char*)(g_kb + ebase);
    const char* vg = (const char*)(g_vb + ebase);

#pragma unroll
    for (int i = 0; i < 8; i++) {
        int s = lane + 32 * i;
        int row = s >> 3, sub = s & 7;
        size_t go = (size_t)row * ROWSTRIDE_B + sub * 16;
        uint32_t so = SMEM_SWIZZLE_128B((uint32_t)(row * 128 + sub * 16));
        cp_async16(qsm + so, qg + go);
        cp_async16(ksm + so, kg + go);
        cp_async16(vsm + so, vg + go);
    }
    cp_commit();
    asm volatile("cp.async.wait_group 0;" ::: "memory");
    __syncwarp();

    int g8 = lane & 7, sel = lane >> 3;

    // ---- S = Q K^T ----
    float c[2][4][4];
#pragma unroll
    for (int mi = 0; mi < 2; mi++)
#pragma unroll
        for (int j = 0; j < 4; j++)
#pragma unroll
            for (int k = 0; k < 4; k++) c[mi][j][k] = 0.f;

#pragma unroll
    for (int kc = 0; kc < 4; kc++) {
        uint32_t kb = kc * 32;
        uint32_t af[2][4], bfr[2][4];
#pragma unroll
        for (int mi = 0; mi < 2; mi++) {
            int row = mi * 16 + g8 + (sel & 1) * 8;
            uint32_t off = row * 128 + ((kb + (sel >> 1) * 16) ^ ((row & 7) << 4));
            ldmx4(af[mi], qsm + off);
        }
#pragma unroll
        for (int nj2 = 0; nj2 < 2; nj2++) {
            int row = nj2 * 16 + g8 + (sel >> 1) * 8;
            uint32_t off = row * 128 + ((kb + (sel & 1) * 16) ^ ((row & 7) << 4));
            ldmx4(bfr[nj2], ksm + off);
        }
#pragma unroll
        for (int mi = 0; mi < 2; mi++)
#pragma unroll
            for (int nj2 = 0; nj2 < 2; nj2++) {
                mma16816f(c[mi][2 * nj2],     af[mi], &bfr[nj2][0]);
                mma16816f(c[mi][2 * nj2 + 1], af[mi], &bfr[nj2][2]);
            }
    }

    // ---- softmax ----
    float inv0[2], inv1[2];
#pragma unroll
    for (int mi = 0; mi < 2; mi++) {
        float m0 = -FLT_MAX, m1 = -FLT_MAX;
#pragma unroll
        for (int j = 0; j < 4; j++) {
#pragma unroll
            for (int k = 0; k < 4; k++) c[mi][j][k] *= 0.125f;
            m0 = fmaxf(m0, fmaxf(c[mi][j][0], c[mi][j][1]));
            m1 = fmaxf(m1, fmaxf(c[mi][j][2], c[mi][j][3]));
        }
        m0 = fmaxf(m0, __shfl_xor_sync(0xffffffffu, m0, 1));
        m0 = fmaxf(m0, __shfl_xor_sync(0xffffffffu, m0, 2));
        m1 = fmaxf(m1, __shfl_xor_sync(0xffffffffu, m1, 1));
        m1 = fmaxf(m1, __shfl_xor_sync(0xffffffffu, m1, 2));
        float s0 = 0.f, s1 = 0.f;
#pragma unroll
        for (int j = 0; j < 4; j++) {
            c[mi][j][0] = __expf(c[mi][j][0] - m0);
            c[mi][j][1] = __expf(c[mi][j][1] - m0);
            c[mi][j][2] = __expf(c[mi][j][2] - m1);
            c[mi][j][3] = __expf(c[mi][j][3] - m1);
            s0 += c[mi][j][0] + c[mi][j][1];
            s1 += c[mi][j][2] + c[mi][j][3];
        }
        s0 += __shfl_xor_sync(0xffffffffu, s0, 1);
        s0 += __shfl_xor_sync(0xffffffffu, s0, 2);
        s1 += __shfl_xor_sync(0xffffffffu, s1, 1);
        s1 += __shfl_xor_sync(0xffffffffu, s1, 2);
        inv0[mi] = 1.f / s0;
        inv1[mi] = 1.f / s1;
    }

    // ---- pack P ----
    uint32_t pf[2][2][4];
#pragma unroll
    for (int mi = 0; mi < 2; mi++)
#pragma unroll
        for (int kc = 0; kc < 2; kc++) {
            __half2 x0 = __floats2half2_rn(c[mi][2 * kc][0],     c[mi][2 * kc][1]);
            __half2 x1 = __floats2half2_rn(c[mi][2 * kc][2],     c[mi][2 * kc][3]);
            __half2 x2 = __floats2half2_rn(c[mi][2 * kc + 1][0], c[mi][2 * kc + 1][1]);
            __half2 x3 = __floats2half2_rn(c[mi][2 * kc + 1][2], c[mi][2 * kc + 1][3]);
            pf[mi][kc][0] = *(uint32_t*)&x0;
            pf[mi][kc][1] = *(uint32_t*)&x1;
            pf[mi][kc][2] = *(uint32_t*)&x2;
            pf[mi][kc][3] = *(uint32_t*)&x3;
        }

    // ---- att = P V ----
    float cv[2][8][4];
#pragma unroll
    for (int mi = 0; mi < 2; mi++)
#pragma unroll
        for (int j = 0; j < 8; j++)
#pragma unroll
            for (int k = 0; k < 4; k++) cv[mi][j][k] = 0.f;

#pragma unroll
    for (int kc = 0; kc < 2; kc++) {
#pragma unroll
        for (int dj2 = 0; dj2 < 4; dj2++) {
            int row = kc * 16 + g8 + (sel & 1) * 8;
            uint32_t colb = dj2 * 32 + (sel >> 1) * 16;
            uint32_t off = row * 128 + (colb ^ ((row & 7) << 4));
            uint32_t bv[4];
            ldmx4t(bv, vsm + off);
#pragma unroll
            for (int mi = 0; mi < 2; mi++) {
                mma16816f(cv[mi][2 * dj2],     pf[mi][kc], &bv[0]);
                mma16816f(cv[mi][2 * dj2 + 1], pf[mi][kc], &bv[2]);
            }
        }
    }

    // ---- normalize + store ----
    int r = lane >> 2, cq = (lane & 3) * 2;
#pragma unroll
    for (int mi = 0; mi < 2; mi++) {
        int i0 = mi * 16 + r;
        __half* o0 = g_qb + ebase + (size_t)i0 * (LSEQ * NHEAD * DHEAD);
        __half* o1 = o0 + (size_t)8 * (LSEQ * NHEAD * DHEAD);
#pragma unroll
        for (int dj = 0; dj < 8; dj++) {
            int col = dj * 8 + cq;
            __half2 h0 = __floats2half2_rn(cv[mi][dj][0] * inv0[mi],
                                           cv[mi][dj][1] * inv0[mi]);
            __half2 h1 = __floats2half2_rn(cv[mi][dj][2] * inv1[mi],
                                           cv[mi][dj][3] * inv1[mi]);
            *(uint32_t*)(o0 + col) = *(uint32_t*)&h0;
            *(uint32_t*)(o1 + col) = *(uint32_t*)&h1;
        }
    }
}

// ---------------------------------------------------------------------------
// 4) Loss
// ---------------------------------------------------------------------------
__global__ void loss_kernel(const int* __restrict__ y,
                            const float* __restrict__ bf,
                            float* __restrict__ out)
{
    if (threadIdx.x != 0 || blockIdx.x != 0) return;
    double s = 0.0;
    double b0 = (double)bf[0], b1 = (double)bf[1];
    for (int b = 0; b < BATCH; b++) {
        double l0 = g_logits[2 * b]     + b0;
        double l1 = g_logits[2 * b + 1] + b1;
        double m  = l0 > l1 ? l0 : l1;
        double lse = m + log(exp(l0 - m) + exp(l1 - m));
        double lp  = (y[b] == 0 ? l0 : l1) - lse;
        s += lp;
    }
    out[0] = (float)(-s / (double)BATCH);
}

// ---------------------------------------------------------------------------
// Launch
// ---------------------------------------------------------------------------
extern "C" void kernel_launch(void* const* d_in, const int* in_sizes, int n_in,
                              void* d_out, int out_size)
{
    const int*   x     = (const int*)d_in[0];
    const int*   y     = (const int*)d_in[1];
    const float* emb   = (const float*)d_in[2];
    const float* Wq    = (const float*)d_in[3];
    const float* Wkv   = (const float*)d_in[4];
    const float* Wo    = (const float*)d_in[5];
    const float* Wf    = (const float*)d_in[6];
    const float* bf    = (const float*)d_in[7];
    float* out = (float*)d_out;

    __half *p_hb, *p_qb, *p_kb, *p_vb, *p_wqkv, *p_wo;
    cudaGetSymbolAddress((void**)&p_hb,   g_hb);
    cudaGetSymbolAddress((void**)&p_qb,   g_qb);
    cudaGetSymbolAddress((void**)&p_kb,   g_kb);
    cudaGetSymbolAddress((void**)&p_vb,   g_vb);
    cudaGetSymbolAddress((void**)&p_wqkv, g_wqkv);
    cudaGetSymbolAddress((void**)&p_wo,   g_wo);

    cudaFuncSetAttribute((void*)gemm_f16_kernel<false, false>,
                         cudaFuncAttributeMaxDynamicSharedMemorySize, GEMM_SMEM);
    cudaFuncSetAttribute((void*)gemm_f16_kernel<true, true>,
                         cudaFuncAttributeMaxDynamicSharedMemorySize, GEMM_SMEM);
    cudaFuncSetAttribute(attn_kernel,
                         cudaFuncAttributeMaxDynamicSharedMemorySize, ATT_SMEM);

    // 1) gather + fused weight prep (also zeroes g_logits)
    gather_kernel<<<ROWS, 256>>>(x, emb);
    dim3 tgrid(32, 32, 4), tblk(256);
    transpose_all_kernel<<<tgrid, tblk>>>(Wq, Wkv, Wo, p_wqkv, p_wo);

    // 2) fused QKV projection: one GEMM, N = 3072
    {
        int nx = 3 * EDIM / NT;              // 24
        gemm_f16_kernel<false, false><<<dim3(nx * (ROWS / MT), 1), 256, GEMM_SMEM>>>(
            p_hb, p_wqkv, nullptr, p_qb, p_kb, p_vb, nullptr, nx);
    }

    // 3) attention (tensor cores; in place: g_qb <- att)
    attn_kernel<<<LSEQ * NHEAD / ATT_WARPS, 256, ATT_SMEM>>>();

    // 4) out = h + att @ Wo, fused with logits = out . Wf  (no g_ob)
    {
        int nx = EDIM / NT;                  // 8
        gemm_f16_kernel<true, true><<<dim3(nx * (ROWS / MT), 1), 256, GEMM_SMEM>>>(
            p_qb, p_wo, p_hb, nullptr, nullptr, nullptr, Wf, nx);
    }

    // 5) loss
    loss_kernel<<<1, 32>>>(y, bf, out);
}

// round 13
// speedup vs baseline: 1.2552x; 1.0014x over previous
#include <cuda_runtime.h>
#include <cuda_fp16.h>
#include <math.h>
#include <float.h>
#include <stdint.h>

// Problem constants
#define BATCH 32
#define LSEQ  2048
#define EDIM  1024
#define NHEAD 16
#define DHEAD 64
#define HD    (NHEAD * DHEAD)     // 1024
#define ROWS  (BATCH * LSEQ)      // 65536
#define FLAT  (LSEQ * EDIM)       // 2097152
#define NCLS  2

#define SMEM_SWIZZLE_128B(byte_offset) \
    ((byte_offset) ^ (((byte_offset) >> 3) & 0x70))

__device__ __forceinline__ uint32_t smem_to_u32(const void* smem_ptr) {
    uint32_t addr;
    asm("{ .reg .u64 tmp; cvta.to.shared.u64 tmp, %1; cvt.u32.u64 %0, tmp; }"
        : "=r"(addr) : "l"(smem_ptr));
    return addr;
}

__device__ __forceinline__ void cp_async16(uint32_t smem_addr, const void* gptr) {
    asm volatile("cp.async.cg.shared.global [%0], [%1], 16;"
                 :: "r"(smem_addr), "l"(gptr) : "memory");
}
__device__ __forceinline__ void cp_commit() {
    asm volatile("cp.async.commit_group;" ::: "memory");
}

__device__ __forceinline__ void ldmx4(uint32_t* r, uint32_t addr) {
    asm volatile("ldmatrix.sync.aligned.m8n8.x4.shared.b16 {%0,%1,%2,%3}, [%4];"
                 : "=r"(r[0]), "=r"(r[1]), "=r"(r[2]), "=r"(r[3]) : "r"(addr));
}
__device__ __forceinline__ void ldmx4t(uint32_t* r, uint32_t addr) {
    asm volatile("ldmatrix.sync.aligned.m8n8.x4.trans.shared.b16 {%0,%1,%2,%3}, [%4];"
                 : "=r"(r[0]), "=r"(r[1]), "=r"(r[2]), "=r"(r[3]) : "r"(addr));
}

// f16 inputs, f16 accumulator
__device__ __forceinline__ void mma16816h(uint32_t* c, const uint32_t* a, const uint32_t* b) {
    asm volatile(
        "mma.sync.aligned.m16n8k16.row.col.f16.f16.f16.f16 "
        "{%0,%1}, {%2,%3,%4,%5}, {%6,%7}, {%0,%1};"
        : "+r"(c[0]), "+r"(c[1])
        : "r"(a[0]), "r"(a[1]), "r"(a[2]), "r"(a[3]), "r"(b[0]), "r"(b[1]));
}

// f16 inputs, f32 accumulator (attention)
__device__ __forceinline__ void mma16816f(float* c, const uint32_t* a, const uint32_t* b) {
    asm volatile(
        "mma.sync.aligned.m16n8k16.row.col.f32.f16.f16.f32 "
        "{%0,%1,%2,%3}, {%4,%5,%6,%7}, {%8,%9}, {%0,%1,%2,%3};"
        : "+f"(c[0]), "+f"(c[1]), "+f"(c[2]), "+f"(c[3])
        : "r"(a[0]), "r"(a[1]), "r"(a[2]), "r"(a[3]), "r"(b[0]), "r"(b[1]));
}

// ---------------------------------------------------------------------------
// Device-global scratch (f16)
// ---------------------------------------------------------------------------
__device__ __half g_hb[(size_t)ROWS * EDIM];     // 128 MB
__device__ __half g_qb[(size_t)ROWS * HD];       // q, then att (in place)
__device__ __half g_kb[(size_t)ROWS * HD];
__device__ __half g_vb[(size_t)ROWS * HD];
__device__ __half g_wqkv[(size_t)3 * HD * EDIM]; // fused Wq^T|Wk^T|Wv^T
__device__ __half g_wo[(size_t)EDIM * HD];
__device__ double g_logits[BATCH * NCLS];

// ---------------------------------------------------------------------------
// 1) MERGED prologue: weight transposes (+logits zero) AND embedding gather
//    in one launch. Blocks [0, 4096): transpose; blocks [4096, 4096+65536):
//    gather. Independent work co-scheduled to overlap DRAM streams.
// ---------------------------------------------------------------------------
#define TRANS_BLOCKS 4096   // 32 x 32 x 4
#define PREP_BLOCKS (TRANS_BLOCKS + ROWS)

__global__ __launch_bounds__(256) void prep_kernel(
    const int* __restrict__ x, const float* __restrict__ emb,
    const float* __restrict__ Wq, const float* __restrict__ Wkv,
    const float* __restrict__ Wo,
    __half* __restrict__ wqkv, __half* __restrict__ wo)
{
    __shared__ float tile[32][33];
    int bid = blockIdx.x;

    if (bid < TRANS_BLOCKS) {
        // ---- weight transpose + convert ----
        int z  = bid >> 10;          // 0..3
        int zi = bid & 1023;
        int bx = (zi & 31) * 32;     // n block
        int by = (zi >> 5) * 32;     // k block

        if (bid == 0 && threadIdx.x < BATCH * NCLS)
            g_logits[threadIdx.x] = 0.0;

        const float* in; int ldin, coloff; __half* out;
        switch (z) {
            case 0: in = Wq;  ldin = HD;     coloff = 0;  out = wqkv;                         break;
            case 1: in = Wkv; ldin = 2 * HD; coloff = 0;  out = wqkv + (size_t)HD * EDIM;     break;
            case 2: in = Wkv; ldin = 2 * HD; coloff = HD; out = wqkv + (size_t)2 * HD * EDIM; break;
            default: in = Wo; ldin = EDIM;   coloff = 0;  out = wo;                           break;
        }
        int tx = threadIdx.x & 31;
        int ty = threadIdx.x >> 5;
        for (int i = ty; i < 32; i += 8)
            tile[i][tx] = in[(size_t)(by + i) * ldin + coloff + bx + tx];
        __syncthreads();
        for (int i = ty; i < 32; i += 8)
            out[(size_t)(bx + i) * 1024 + by + tx] = __float2half(tile[tx][i]);
    } else {
        // ---- embedding gather -> f16 ----
        int row = bid - TRANS_BLOCKS;
        int v = x[row];
        int t = threadIdx.x;
        float4 f = ((const float4*)(emb + (size_t)v * EDIM))[t];
        __half2 lo = __floats2half2_rn(f.x, f.y);
        __half2 hi = __floats2half2_rn(f.z, f.w);
        uint2 p;
        p.x = *(uint32_t*)&lo;
        p.y = *(uint32_t*)&hi;
        ((uint2*)(g_hb + (size_t)row * EDIM))[t] = p;
    }
}

// ---------------------------------------------------------------------------
// 2) f16 tensor-core GEMM (128x128, 256 thr, 3-stage, 2 CTA/SM).
//    LOGITS variant: epilogue dots (acc+res) with Wf -> g_logits atomics.
//    Raster: GEMM1 groups 8 y-blocks per x-stripe (B reuse). GEMM2/LOGITS
//    orders tiles (lblk, bx, b) with b innermost so the 32 batch-tiles that
//    share one Wf slice run in the same wave (Wf read from DRAM once).
// ---------------------------------------------------------------------------
#define MT 128
#define NT 128
#define A_BYTES (MT * 128)          // 16 KB per K-chunk of 64
#define B_BYTES (NT * 128)          // 16 KB
#define NCHUNKS 16
#define STAGES 3
#define GEMM_SMEM (STAGES * (A_BYTES + B_BYTES) + 1024)   // 99328

__device__ __forceinline__ void load_chunk(
    uint32_t abuf, uint32_t bbuf,
    const char* Abase, const char* Bbase, int c, int t)
{
#pragma unroll
    for (int i = 0; i < 4; i++) {
        int seg = t + 256 * i;
        int r = seg >> 3, s = seg & 7;
        uint32_t off = SMEM_SWIZZLE_128B((uint32_t)(r * 128 + s * 16));
        cp_async16(abuf + off, Abase + (size_t)r * 2048 + c * 128 + s * 16);
    }
#pragma unroll
    for (int i = 0; i < 4; i++) {
        int seg = t + 256 * i;
        int r = seg >> 3, s = seg & 7;
        uint32_t off = SMEM_SWIZZLE_128B((uint32_t)(r * 128 + s * 16));
        cp_async16(bbuf + off, Bbase + (size_t)r * 2048 + c * 128 + s * 16);
    }
}

template<bool RES, bool LOGITS>
__global__ __launch_bounds__(256, 2) void gemm_f16_kernel(
    const __half* __restrict__ A,
    const __half* __restrict__ Bt,
    const __half* __restrict__ Res,
    __half* __restrict__ D0,
    __half* __restrict__ D1,
    __half* __restrict__ D2,
    const float* __restrict__ Wf,
    int nxblocks)
{
    extern __shared__ char smem[];
    uint32_t base = (smem_to_u32(smem) + 1023) & ~1023u;
    uint32_t a_sm[STAGES], b_sm[STAGES];
#pragma unroll
    for (int s = 0; s < STAGES; s++) {
        a_sm[s] = base + s * (A_BYTES + B_BYTES);
        b_sm[s] = a_sm[s] + A_BYTES;
    }

    int t = threadIdx.x;
    int wid = t >> 5, lane = t & 31;
    int mwarp0 = (wid & 3) * 32;
    int nwarp0 = (wid >> 2) * 64;

    int bid = blockIdx.x;
    int bx, by;
    if (LOGITS) {
        // nxblocks == 8; order (lblk, bx, b), b innermost -> Wf slice reuse
        int b    = bid & 31;
        bx       = (bid >> 5) & 7;
        int lblk = bid >> 8;            // 0..15
        by = b * 16 + lblk;
    } else {
        int group = bid / (nxblocks * 8);
        int rem   = bid % (nxblocks * 8);
        bx = rem % nxblocks;
        by = group * 8 + (rem / nxblocks);
    }

    size_t row0 = (size_t)by * MT;
    int col0 = bx * NT;

    int tgt = col0 >> 10;
    int colc = col0 & 1023;
    __half* D = (tgt == 0) ? D0 : ((tgt == 1) ? D1 : D2);

    const char* Abase = (const char*)(A + row0 * 1024);
    const char* Bbase = (const char*)(Bt + (size_t)col0 * 1024);

    // per-lane ldmatrix address components
    int g = lane & 7, sel = lane >> 3;
    int mA = mwarp0 + g + (sel & 1) * 8;
    uint32_t aRow[2] = { (uint32_t)(mA * 128), (uint32_t)((mA + 16) * 128) };
    uint32_t aKb = (uint32_t)((sel >> 1) * 16);
    uint32_t aX  = (uint32_t)((mA & 7) << 4);

    int nB = nwarp0 + g + ((sel >> 1) * 8);
    uint32_t bRow[4] = { (uint32_t)(nB * 128), (uint32_t)((nB + 16) * 128),
                         (uint32_t)((nB + 32) * 128), (uint32_t)((nB + 48) * 128) };
    uint32_t bKb = (uint32_t)((sel & 1) * 16);
    uint32_t bX  = (uint32_t)((nB & 7) << 4);

    uint32_t hacc[2][8][2];
#pragma unroll
    for (int i = 0; i < 2; i++)
#pragma unroll
        for (int j = 0; j < 8; j++) { hacc[i][j][0] = 0u; hacc[i][j][1] = 0u; }

    load_chunk(a_sm[0], b_sm[0], Abase, Bbase, 0, t); cp_commit();
    load_chunk(a_sm[1], b_sm[1], Abase, Bbase, 1, t); cp_commit();

#pragma unroll
    for (int c = 0; c < NCHUNKS; c++) {
        int stage = c % STAGES;
        if (c < NCHUNKS - 1) {
            asm volatile("cp.async.wait_group 1;" ::: "memory");
        } else {
            asm volatile("cp.async.wait_group 0;" ::: "memory");
        }
        __syncthreads();
        if (c + 2 < NCHUNKS) {
            int ns = (c + 2) % STAGES;
            load_chunk(a_sm[ns], b_sm[ns], Abase, Bbase, c + 2, t);
            cp_commit();
        }

        uint32_t ab = a_sm[stage], bb = b_sm[stage];
#pragma unroll
        for (int s = 0; s < 4; s++) {
            uint32_t kb0 = (uint32_t)(s * 32);
            uint32_t afrag[2][4], bfrag[4][4];
#pragma unroll
            for (int mi = 0; mi < 2; mi++)
                ldmx4(afrag[mi], ab + aRow[mi] + ((aKb + kb0) ^ aX));
#pragma unroll
            for (int j = 0; j < 4; j++)
                ldmx4(bfrag[j], bb + bRow[j] + ((bKb + kb0) ^ bX));
#pragma unroll
            for (int mi = 0; mi < 2; mi++)
#pragma unroll
                for (int j = 0; j < 4; j++) {
                    mma16816h(hacc[mi][2 * j],     afrag[mi], &bfrag[j][0]);
                    mma16816h(hacc[mi][2 * j + 1], afrag[mi], &bfrag[j][2]);
                }
        }
    }

    if (!LOGITS) {
        // Standard epilogue: packed half2 stores (+ optional residual)
#pragma unroll
        for (int mi = 0; mi < 2; mi++) {
            size_t r0 = row0 + mwarp0 + mi * 16 + (lane >> 2);
#pragma unroll
            for (int nj = 0; nj < 8; nj++) {
                int col = colc + nwarp0 + nj * 8 + (lane & 3) * 2;
                uint32_t v0 = hacc[mi][nj][0];
                uint32_t v1 = hacc[mi][nj][1];
                if (RES) {
                    uint32_t u0 = *(const uint32_t*)(Res + r0 * 1024 + col);
                    uint32_t u1 = *(const uint32_t*)(Res + (r0 + 8) * 1024 + col);
                    __half2 a0 = __hadd2(*(__half2*)&v0, *(__half2*)&u0);
                    __half2 a1 = __hadd2(*(__half2*)&v1, *(__half2*)&u1);
                    v0 = *(uint32_t*)&a0;
                    v1 = *(uint32_t*)&a1;
                }
                *(uint32_t*)(D + r0 * 1024 + col)       = v0;
                *(uint32_t*)(D + (r0 + 8) * 1024 + col) = v1;
            }
        }
    } else {
        // Fused-logits epilogue: out = acc + res (f32); dot with Wf; reduce.
        float a0 = 0.f, a1 = 0.f;
        int bidx = (int)(row0 >> 11);   // 2048 rows per batch
#pragma unroll
        for (int mi = 0; mi < 2; mi++) {
            size_t r0 = row0 + mwarp0 + mi * 16 + (lane >> 2);
            int l0 = (int)(r0 & 2047);
#pragma unroll
            for (int nj = 0; nj < 8; nj++) {
                int col = colc + nwarp0 + nj * 8 + (lane & 3) * 2;
                uint32_t v0 = hacc[mi][nj][0];
                uint32_t v1 = hacc[mi][nj][1];
                uint32_t u0 = *(const uint32_t*)(Res + r0 * 1024 + col);
                uint32_t u1 = *(const uint32_t*)(Res + (r0 + 8) * 1024 + col);
                __half2 s0 = __hadd2(*(__half2*)&v0, *(__half2*)&u0);
                __half2 s1 = __hadd2(*(__half2*)&v1, *(__half2*)&u1);
                float2 f0 = __half22float2(s0);
                float2 f1 = __half22float2(s1);
                const float4 w0 = *(const float4*)(Wf + ((size_t)l0 * 1024 + col) * 2);
                const float4 w1 = *(const float4*)(Wf + ((size_t)(l0 + 8) * 1024 + col) * 2);
                a0 += f0.x * w0.x + f0.y * w0.z + f1.x * w1.x + f1.y * w1.z;
                a1 += f0.x * w0.y + f0.y * w0.w + f1.x * w1.y + f1.y * w1.w;
            }
        }
#pragma unroll
        for (int off = 16; off >= 1; off >>= 1) {
            a0 += __shfl_xor_sync(0xffffffffu, a0, off);
            a1 += __shfl_xor_sync(0xffffffffu, a1, off);
        }
        __shared__ float red[8][2];
        if (lane == 0) { red[wid][0] = a0; red[wid][1] = a1; }
        __syncthreads();
        if (t == 0) {
            float s0 = 0.f, s1 = 0.f;
#pragma unroll
            for (int wv = 0; wv < 8; wv++) { s0 += red[wv][0]; s1 += red[wv][1]; }
            atomicAdd(&g_logits[2 * bidx],     (double)s0);
            atomicAdd(&g_logits[2 * bidx + 1], (double)s1);
        }
    }
}

// ---------------------------------------------------------------------------
// 3) Attention on tensor cores (f16 in/out, f32 softmax accum).
// ---------------------------------------------------------------------------
#define ATT_WARPS 8
#define ATT_SMEM (ATT_WARPS * 3 * 4096)   // 96 KB
#define ROWSTRIDE_B (LSEQ * NHEAD * DHEAD * 2)  // batch-row stride in bytes

__global__ __launch_bounds__(256) void attn_kernel()
{
    extern __shared__ char asmem[];
    int t = threadIdx.x, w = t >> 5, lane = t & 31;
    uint32_t wbase = smem_to_u32(asmem) + w * 12288;
    uint32_t qsm = wbase, ksm = wbase + 4096, vsm = wbase + 8192;

    int pair = blockIdx.x * ATT_WARPS + w;
    int l = pair >> 4, n = pair & 15;
    size_t ebase = ((size_t)l * NHEAD + n) * DHEAD;
    const char* qg = (const char*)(g_qb + ebase);
    const char* kg = (const char*)(g_kb + ebase);
    const char* vg = (const char*)(g_vb + ebase);

#pragma unroll
    for (int i = 0; i < 8; i++) {
        int s = lane + 32 * i;
        int row = s >> 3, sub = s & 7;
        size_t go = (size_t)row * ROWSTRIDE_B + sub * 16;
        uint32_t so = SMEM_SWIZZLE_128B((uint32_t)(row * 128 + sub * 16));
        cp_async16(qsm + so, qg + go);
        cp_async16(ksm + so, kg + go);
        cp_async16(vsm + so, vg + go);
    }
    cp_commit();
    asm volatile("cp.async.wait_group 0;" ::: "memory");
    __syncwarp();

    int g8 = lane & 7, sel = lane >> 3;

    // ---- S = Q K^T ----
    float c[2][4][4];
#pragma unroll
    for (int mi = 0; mi < 2; mi++)
#pragma unroll
        for (int j = 0; j < 4; j++)
#pragma unroll
            for (int k = 0; k < 4; k++) c[mi][j][k] = 0.f;

#pragma unroll
    for (int kc = 0; kc < 4; kc++) {
        uint32_t kb = kc * 32;
        uint32_t af[2][4], bfr[2][4];
#pragma unroll
        for (int mi = 0; mi < 2; mi++) {
            int row = mi * 16 + g8 + (sel & 1) * 8;
            uint32_t off = row * 128 + ((kb + (sel >> 1) * 16) ^ ((row & 7) << 4));
            ldmx4(af[mi], qsm + off);
        }
#pragma unroll
        for (int nj2 = 0; nj2 < 2; nj2++) {
            int row = nj2 * 16 + g8 + (sel >> 1) * 8;
            uint32_t off = row * 128 + ((kb + (sel & 1) * 16) ^ ((row & 7) << 4));
            ldmx4(bfr[nj2], ksm + off);
        }
#pragma unroll
        for (int mi = 0; mi < 2; mi++)
#pragma unroll
            for (int nj2 = 0; nj2 < 2; nj2++) {
                mma16816f(c[mi][2 * nj2],     af[mi], &bfr[nj2][0]);
                mma16816f(c[mi][2 * nj2 + 1], af[mi], &bfr[nj2][2]);
            }
    }

    // ---- softmax ----
    float inv0[2], inv1[2];
#pragma unroll
    for (int mi = 0; mi < 2; mi++) {
        float m0 = -FLT_MAX, m1 = -FLT_MAX;
#pragma unroll
        for (int j = 0; j < 4; j++) {
#pragma unroll
            for (int k = 0; k < 4; k++) c[mi][j][k] *= 0.125f;
            m0 = fmaxf(m0, fmaxf(c[mi][j][0], c[mi][j][1]));
            m1 = fmaxf(m1, fmaxf(c[mi][j][2], c[mi][j][3]));
        }
        m0 = fmaxf(m0, __shfl_xor_sync(0xffffffffu, m0, 1));
        m0 = fmaxf(m0, __shfl_xor_sync(0xffffffffu, m0, 2));
        m1 = fmaxf(m1, __shfl_xor_sync(0xffffffffu, m1, 1));
        m1 = fmaxf(m1, __shfl_xor_sync(0xffffffffu, m1, 2));
        float s0 = 0.f, s1 = 0.f;
#pragma unroll
        for (int j = 0; j < 4; j++) {
            c[mi][j][0] = __expf(c[mi][j][0] - m0);
            c[mi][j][1] = __expf(c[mi][j][1] - m0);
            c[mi][j][2] = __expf(c[mi][j][2] - m1);
            c[mi][j][3] = __expf(c[mi][j][3] - m1);
            s0 += c[mi][j][0] + c[mi][j][1];
            s1 += c[mi][j][2] + c[mi][j][3];
        }
        s0 += __shfl_xor_sync(0xffffffffu, s0, 1);
        s0 += __shfl_xor_sync(0xffffffffu, s0, 2);
        s1 += __shfl_xor_sync(0xffffffffu, s1, 1);
        s1 += __shfl_xor_sync(0xffffffffu, s1, 2);
        inv0[mi] = 1.f / s0;
        inv1[mi] = 1.f / s1;
    }

    // ---- pack P ----
    uint32_t pf[2][2][4];
#pragma unroll
    for (int mi = 0; mi < 2; mi++)
#pragma unroll
        for (int kc = 0; kc < 2; kc++) {
            __half2 x0 = __floats2half2_rn(c[mi][2 * kc][0],     c[mi][2 * kc][1]);
            __half2 x1 = __floats2half2_rn(c[mi][2 * kc][2],     c[mi][2 * kc][3]);
            __half2 x2 = __floats2half2_rn(c[mi][2 * kc + 1][0], c[mi][2 * kc + 1][1]);
            __half2 x3 = __floats2half2_rn(c[mi][2 * kc + 1][2], c[mi][2 * kc + 1][3]);
            pf[mi][kc][0] = *(uint32_t*)&x0;
            pf[mi][kc][1] = *(uint32_t*)&x1;
            pf[mi][kc][2] = *(uint32_t*)&x2;
            pf[mi][kc][3] = *(uint32_t*)&x3;
        }

    // ---- att = P V ----
    float cv[2][8][4];
#pragma unroll
    for (int mi = 0; mi < 2; mi++)
#pragma unroll
        for (int j = 0; j < 8; j++)
#pragma unroll
            for (int k = 0; k < 4; k++) cv[mi][j][k] = 0.f;

#pragma unroll
    for (int kc = 0; kc < 2; kc++) {
#pragma unroll
        for (int dj2 = 0; dj2 < 4; dj2++) {
            int row = kc * 16 + g8 + (sel & 1) * 8;
            uint32_t colb = dj2 * 32 + (sel >> 1) * 16;
            uint32_t off = row * 128 + (colb ^ ((row & 7) << 4));
            uint32_t bv[4];
            ldmx4t(bv, vsm + off);
#pragma unroll
            for (int mi = 0; mi < 2; mi++) {
                mma16816f(cv[mi][2 * dj2],     pf[mi][kc], &bv[0]);
                mma16816f(cv[mi][2 * dj2 + 1], pf[mi][kc], &bv[2]);
            }
        }
    }

    // ---- normalize + store ----
    int r = lane >> 2, cq = (lane & 3) * 2;
#pragma unroll
    for (int mi = 0; mi < 2; mi++) {
        int i0 = mi * 16 + r;
        __half* o0 = g_qb + ebase + (size_t)i0 * (LSEQ * NHEAD * DHEAD);
        __half* o1 = o0 + (size_t)8 * (LSEQ * NHEAD * DHEAD);
#pragma unroll
        for (int dj = 0; dj < 8; dj++) {
            int col = dj * 8 + cq;
            __half2 h0 = __floats2half2_rn(cv[mi][dj][0] * inv0[mi],
                                           cv[mi][dj][1] * inv0[mi]);
            __half2 h1 = __floats2half2_rn(cv[mi][dj][2] * inv1[mi],
                                           cv[mi][dj][3] * inv1[mi]);
            *(uint32_t*)(o0 + col) = *(uint32_t*)&h0;
            *(uint32_t*)(o1 + col) = *(uint32_t*)&h1;
        }
    }
}

// ---------------------------------------------------------------------------
// 4) Loss
// ---------------------------------------------------------------------------
__global__ void loss_kernel(const int* __restrict__ y,
                            const float* __restrict__ bf,
                            float* __restrict__ out)
{
    if (threadIdx.x != 0 || blockIdx.x != 0) return;
    double s = 0.0;
    double b0 = (double)bf[0], b1 = (double)bf[1];
    for (int b = 0; b < BATCH; b++) {
        double l0 = g_logits[2 * b]     + b0;
        double l1 = g_logits[2 * b + 1] + b1;
        double m  = l0 > l1 ? l0 : l1;
        double lse = m + log(exp(l0 - m) + exp(l1 - m));
        double lp  = (y[b] == 0 ? l0 : l1) - lse;
        s += lp;
    }
    out[0] = (float)(-s / (double)BATCH);
}

// ---------------------------------------------------------------------------
// Launch
// ---------------------------------------------------------------------------
extern "C" void kernel_launch(void* const* d_in, const int* in_sizes, int n_in,
                              void* d_out, int out_size)
{
    const int*   x     = (const int*)d_in[0];
    const int*   y     = (const int*)d_in[1];
    const float* emb   = (const float*)d_in[2];
    const float* Wq    = (const float*)d_in[3];
    const float* Wkv   = (const float*)d_in[4];
    const float* Wo    = (const float*)d_in[5];
    const float* Wf    = (const float*)d_in[6];
    const float* bf    = (const float*)d_in[7];
    float* out = (float*)d_out;

    __half *p_hb, *p_qb, *p_kb, *p_vb, *p_wqkv, *p_wo;
    cudaGetSymbolAddress((void**)&p_hb,   g_hb);
    cudaGetSymbolAddress((void**)&p_qb,   g_qb);
    cudaGetSymbolAddress((void**)&p_kb,   g_kb);
    cudaGetSymbolAddress((void**)&p_vb,   g_vb);
    cudaGetSymbolAddress((void**)&p_wqkv, g_wqkv);
    cudaGetSymbolAddress((void**)&p_wo,   g_wo);

    cudaFuncSetAttribute((void*)gemm_f16_kernel<false, false>,
                         cudaFuncAttributeMaxDynamicSharedMemorySize, GEMM_SMEM);
    cudaFuncSetAttribute((void*)gemm_f16_kernel<true, true>,
                         cudaFuncAttributeMaxDynamicSharedMemorySize, GEMM_SMEM);
    cudaFuncSetAttribute(attn_kernel,
                         cudaFuncAttributeMaxDynamicSharedMemorySize, ATT_SMEM);

    // 1) merged prologue: transposes + logits zero + embedding gather
    prep_kernel<<<PREP_BLOCKS, 256>>>(x, emb, Wq, Wkv, Wo, p_wqkv, p_wo);

    // 2) fused QKV projection: one GEMM, N = 3072
    {
        int nx = 3 * EDIM / NT;              // 24
        gemm_f16_kernel<false, false><<<dim3(nx * (ROWS / MT), 1), 256, GEMM_SMEM>>>(
            p_hb, p_wqkv, nullptr, p_qb, p_kb, p_vb, nullptr, nx);
    }

    // 3) attention (tensor cores; in place: g_qb <- att)
    attn_kernel<<<LSEQ * NHEAD / ATT_WARPS, 256, ATT_SMEM>>>();

    // 4) out = h + att @ Wo, fused with logits = out . Wf  (no g_ob)
    {
        int nx = EDIM / NT;                  // 8
        gemm_f16_kernel<true, true><<<dim3(nx * (ROWS / MT), 1), 256, GEMM_SMEM>>>(
            p_qb, p_wo, p_hb, nullptr, nullptr, nullptr, Wf, nx);
    }

    // 5) loss
    loss_kernel<<<1, 32>>>(y, bf, out);
}

// round 14
// speedup vs baseline: 1.2871x; 1.0254x over previous
#include <cuda_runtime.h>
#include <cuda_fp16.h>
#include <math.h>
#include <float.h>
#include <stdint.h>

// Problem constants
#define BATCH 32
#define LSEQ  2048
#define EDIM  1024
#define NHEAD 16
#define DHEAD 64
#define HD    (NHEAD * DHEAD)     // 1024
#define ROWS  (BATCH * LSEQ)      // 65536
#define FLAT  (LSEQ * EDIM)       // 2097152
#define NCLS  2

#define SMEM_SWIZZLE_128B(byte_offset) \
    ((byte_offset) ^ (((byte_offset) >> 3) & 0x70))

__device__ __forceinline__ uint32_t smem_to_u32(const void* smem_ptr) {
    uint32_t addr;
    asm("{ .reg .u64 tmp; cvta.to.shared.u64 tmp, %1; cvt.u32.u64 %0, tmp; }"
        : "=r"(addr) : "l"(smem_ptr));
    return addr;
}

__device__ __forceinline__ void cp_async16(uint32_t smem_addr, const void* gptr) {
    asm volatile("cp.async.cg.shared.global [%0], [%1], 16;"
                 :: "r"(smem_addr), "l"(gptr) : "memory");
}
__device__ __forceinline__ void cp_commit() {
    asm volatile("cp.async.commit_group;" ::: "memory");
}

__device__ __forceinline__ void ldmx4(uint32_t* r, uint32_t addr) {
    asm volatile("ldmatrix.sync.aligned.m8n8.x4.shared.b16 {%0,%1,%2,%3}, [%4];"
                 : "=r"(r[0]), "=r"(r[1]), "=r"(r[2]), "=r"(r[3]) : "r"(addr));
}
__device__ __forceinline__ void ldmx4t(uint32_t* r, uint32_t addr) {
    asm volatile("ldmatrix.sync.aligned.m8n8.x4.trans.shared.b16 {%0,%1,%2,%3}, [%4];"
                 : "=r"(r[0]), "=r"(r[1]), "=r"(r[2]), "=r"(r[3]) : "r"(addr));
}

// f16 inputs, f16 accumulator
__device__ __forceinline__ void mma16816h(uint32_t* c, const uint32_t* a, const uint32_t* b) {
    asm volatile(
        "mma.sync.aligned.m16n8k16.row.col.f16.f16.f16.f16 "
        "{%0,%1}, {%2,%3,%4,%5}, {%6,%7}, {%0,%1};"
        : "+r"(c[0]), "+r"(c[1])
        : "r"(a[0]), "r"(a[1]), "r"(a[2]), "r"(a[3]), "r"(b[0]), "r"(b[1]));
}

// f16 inputs, f32 accumulator (attention)
__device__ __forceinline__ void mma16816f(float* c, const uint32_t* a, const uint32_t* b) {
    asm volatile(
        "mma.sync.aligned.m16n8k16.row.col.f32.f16.f16.f32 "
        "{%0,%1,%2,%3}, {%4,%5,%6,%7}, {%8,%9}, {%0,%1,%2,%3};"
        : "+f"(c[0]), "+f"(c[1]), "+f"(c[2]), "+f"(c[3])
        : "r"(a[0]), "r"(a[1]), "r"(a[2]), "r"(a[3]), "r"(b[0]), "r"(b[1]));
}

// ---------------------------------------------------------------------------
// Device-global scratch (f16)
// ---------------------------------------------------------------------------
__device__ __half g_hb[(size_t)ROWS * EDIM];     // 128 MB
__device__ __half g_qb[(size_t)ROWS * HD];       // q, then att (in place)
__device__ __half g_kb[(size_t)ROWS * HD];
__device__ __half g_vb[(size_t)ROWS * HD];
__device__ __half g_wqkv[(size_t)3 * HD * EDIM]; // fused Wq^T|Wk^T|Wv^T
__device__ __half g_wo[(size_t)EDIM * HD];
__device__ __half g_wf16[(size_t)FLAT * NCLS];   // 8 MB (f16 copy of Wf)
__device__ double g_logits[BATCH * NCLS];

// ---------------------------------------------------------------------------
// 1) MERGED prologue: weight transposes (+logits zero), Wf f32->f16 convert,
//    AND embedding gather, in one launch.
//    blocks [0, 4096): transpose; [4096, 6144): Wf convert; rest: gather.
// ---------------------------------------------------------------------------
#define TRANS_BLOCKS 4096          // 32 x 32 x 4
#define WF_BLOCKS    2048          // 2048 blocks x 2048 floats = 4194304
#define PREP_BLOCKS  (TRANS_BLOCKS + WF_BLOCKS + ROWS)

__global__ __launch_bounds__(256) void prep_kernel(
    const int* __restrict__ x, const float* __restrict__ emb,
    const float* __restrict__ Wq, const float* __restrict__ Wkv,
    const float* __restrict__ Wo, const float* __restrict__ Wf,
    __half* __restrict__ wqkv, __half* __restrict__ wo)
{
    __shared__ float tile[32][33];
    int bid = blockIdx.x;

    if (bid < TRANS_BLOCKS) {
        // ---- weight transpose + convert ----
        int z  = bid >> 10;          // 0..3
        int zi = bid & 1023;
        int bx = (zi & 31) * 32;     // n block
        int by = (zi >> 5) * 32;     // k block

        if (bid == 0 && threadIdx.x < BATCH * NCLS)
            g_logits[threadIdx.x] = 0.0;

        const float* in; int ldin, coloff; __half* out;
        switch (z) {
            case 0: in = Wq;  ldin = HD;     coloff = 0;  out = wqkv;                         break;
            case 1: in = Wkv; ldin = 2 * HD; coloff = 0;  out = wqkv + (size_t)HD * EDIM;     break;
            case 2: in = Wkv; ldin = 2 * HD; coloff = HD; out = wqkv + (size_t)2 * HD * EDIM; break;
            default: in = Wo; ldin = EDIM;   coloff = 0;  out = wo;                           break;
        }
        int tx = threadIdx.x & 31;
        int ty = threadIdx.x >> 5;
        for (int i = ty; i < 32; i += 8)
            tile[i][tx] = in[(size_t)(by + i) * ldin + coloff + bx + tx];
        __syncthreads();
        for (int i = ty; i < 32; i += 8)
            out[(size_t)(bx + i) * 1024 + by + tx] = __float2half(tile[tx][i]);
    } else if (bid < TRANS_BLOCKS + WF_BLOCKS) {
        // ---- Wf f32 -> f16 ----
        size_t base = (size_t)(bid - TRANS_BLOCKS) * 2048 + (size_t)threadIdx.x * 8;
        float4 f0 = *(const float4*)(Wf + base);
        float4 f1 = *(const float4*)(Wf + base + 4);
        __half2 h0 = __floats2half2_rn(f0.x, f0.y);
        __half2 h1 = __floats2half2_rn(f0.z, f0.w);
        __half2 h2 = __floats2half2_rn(f1.x, f1.y);
        __half2 h3 = __floats2half2_rn(f1.z, f1.w);
        uint4 o;
        o.x = *(uint32_t*)&h0; o.y = *(uint32_t*)&h1;
        o.z = *(uint32_t*)&h2; o.w = *(uint32_t*)&h3;
        *(uint4*)(g_wf16 + base) = o;
    } else {
        // ---- embedding gather -> f16 ----
        int row = bid - TRANS_BLOCKS - WF_BLOCKS;
        int v = x[row];
        int t = threadIdx.x;
        float4 f = ((const float4*)(emb + (size_t)v * EDIM))[t];
        __half2 lo = __floats2half2_rn(f.x, f.y);
        __half2 hi = __floats2half2_rn(f.z, f.w);
        uint2 p;
        p.x = *(uint32_t*)&lo;
        p.y = *(uint32_t*)&hi;
        ((uint2*)(g_hb + (size_t)row * EDIM))[t] = p;
    }
}

// ---------------------------------------------------------------------------
// 2) f16 tensor-core GEMM (128x128, 256 thr, 3-stage, 2 CTA/SM).
//    LOGITS variant: epilogue dots (acc+res) with f16 Wf -> g_logits atomics
//    (per-warp, no smem reduce). Raster: GEMM1 groups 8 y per x-stripe;
//    LOGITS orders (lblk, bx, b) with b innermost for Wf slice reuse.
// ---------------------------------------------------------------------------
#define MT 128
#define NT 128
#define A_BYTES (MT * 128)          // 16 KB per K-chunk of 64
#define B_BYTES (NT * 128)          // 16 KB
#define NCHUNKS 16
#define STAGES 3
#define GEMM_SMEM (STAGES * (A_BYTES + B_BYTES) + 1024)   // 99328

__device__ __forceinline__ void load_chunk(
    uint32_t abuf, uint32_t bbuf,
    const char* Abase, const char* Bbase, int c, int t)
{
#pragma unroll
    for (int i = 0; i < 4; i++) {
        int seg = t + 256 * i;
        int r = seg >> 3, s = seg & 7;
        uint32_t off = SMEM_SWIZZLE_128B((uint32_t)(r * 128 + s * 16));
        cp_async16(abuf + off, Abase + (size_t)r * 2048 + c * 128 + s * 16);
    }
#pragma unroll
    for (int i = 0; i < 4; i++) {
        int seg = t + 256 * i;
        int r = seg >> 3, s = seg & 7;
        uint32_t off = SMEM_SWIZZLE_128B((uint32_t)(r * 128 + s * 16));
        cp_async16(bbuf + off, Bbase + (size_t)r * 2048 + c * 128 + s * 16);
    }
}

template<bool RES, bool LOGITS>
__global__ __launch_bounds__(256, 2) void gemm_f16_kernel(
    const __half* __restrict__ A,
    const __half* __restrict__ Bt,
    const __half* __restrict__ Res,
    __half* __restrict__ D0,
    __half* __restrict__ D1,
    __half* __restrict__ D2,
    int nxblocks)
{
    extern __shared__ char smem[];
    uint32_t base = (smem_to_u32(smem) + 1023) & ~1023u;
    uint32_t a_sm[STAGES], b_sm[STAGES];
#pragma unroll
    for (int s = 0; s < STAGES; s++) {
        a_sm[s] = base + s * (A_BYTES + B_BYTES);
        b_sm[s] = a_sm[s] + A_BYTES;
    }

    int t = threadIdx.x;
    int wid = t >> 5, lane = t & 31;
    int mwarp0 = (wid & 3) * 32;
    int nwarp0 = (wid >> 2) * 64;

    int bid = blockIdx.x;
    int bx, by;
    if (LOGITS) {
        // nxblocks == 8; order (lblk, bx, b), b innermost -> Wf slice reuse
        int b    = bid & 31;
        bx       = (bid >> 5) & 7;
        int lblk = bid >> 8;            // 0..15
        by = b * 16 + lblk;
    } else {
        int group = bid / (nxblocks * 8);
        int rem   = bid % (nxblocks * 8);
        bx = rem % nxblocks;
        by = group * 8 + (rem / nxblocks);
    }

    size_t row0 = (size_t)by * MT;
    int col0 = bx * NT;

    int tgt = col0 >> 10;
    int colc = col0 & 1023;
    __half* D = (tgt == 0) ? D0 : ((tgt == 1) ? D1 : D2);

    const char* Abase = (const char*)(A + row0 * 1024);
    const char* Bbase = (const char*)(Bt + (size_t)col0 * 1024);

    // per-lane ldmatrix address components
    int g = lane & 7, sel = lane >> 3;
    int mA = mwarp0 + g + (sel & 1) * 8;
    uint32_t aRow[2] = { (uint32_t)(mA * 128), (uint32_t)((mA + 16) * 128) };
    uint32_t aKb = (uint32_t)((sel >> 1) * 16);
    uint32_t aX  = (uint32_t)((mA & 7) << 4);

    int nB = nwarp0 + g + ((sel >> 1) * 8);
    uint32_t bRow[4] = { (uint32_t)(nB * 128), (uint32_t)((nB + 16) * 128),
                         (uint32_t)((nB + 32) * 128), (uint32_t)((nB + 48) * 128) };
    uint32_t bKb = (uint32_t)((sel & 1) * 16);
    uint32_t bX  = (uint32_t)((nB & 7) << 4);

    uint32_t hacc[2][8][2];
#pragma unroll
    for (int i = 0; i < 2; i++)
#pragma unroll
        for (int j = 0; j < 8; j++) { hacc[i][j][0] = 0u; hacc[i][j][1] = 0u; }

    load_chunk(a_sm[0], b_sm[0], Abase, Bbase, 0, t); cp_commit();
    load_chunk(a_sm[1], b_sm[1], Abase, Bbase, 1, t); cp_commit();

#pragma unroll
    for (int c = 0; c < NCHUNKS; c++) {
        int stage = c % STAGES;
        if (c < NCHUNKS - 1) {
            asm volatile("cp.async.wait_group 1;" ::: "memory");
        } else {
            asm volatile("cp.async.wait_group 0;" ::: "memory");
        }
        __syncthreads();
        if (c + 2 < NCHUNKS) {
            int ns = (c + 2) % STAGES;
            load_chunk(a_sm[ns], b_sm[ns], Abase, Bbase, c + 2, t);
            cp_commit();
        }

        uint32_t ab = a_sm[stage], bb = b_sm[stage];
#pragma unroll
        for (int s = 0; s < 4; s++) {
            uint32_t kb0 = (uint32_t)(s * 32);
            uint32_t afrag[2][4], bfrag[4][4];
#pragma unroll
            for (int mi = 0; mi < 2; mi++)
                ldmx4(afrag[mi], ab + aRow[mi] + ((aKb + kb0) ^ aX));
#pragma unroll
            for (int j = 0; j < 4; j++)
                ldmx4(bfrag[j], bb + bRow[j] + ((bKb + kb0) ^ bX));
#pragma unroll
            for (int mi = 0; mi < 2; mi++)
#pragma unroll
                for (int j = 0; j < 4; j++) {
                    mma16816h(hacc[mi][2 * j],     afrag[mi], &bfrag[j][0]);
                    mma16816h(hacc[mi][2 * j + 1], afrag[mi], &bfrag[j][2]);
                }
        }
    }

    if (!LOGITS) {
        // Standard epilogue: packed half2 stores (+ optional residual)
#pragma unroll
        for (int mi = 0; mi < 2; mi++) {
            size_t r0 = row0 + mwarp0 + mi * 16 + (lane >> 2);
#pragma unroll
            for (int nj = 0; nj < 8; nj++) {
                int col = colc + nwarp0 + nj * 8 + (lane & 3) * 2;
                uint32_t v0 = hacc[mi][nj][0];
                uint32_t v1 = hacc[mi][nj][1];
                if (RES) {
                    uint32_t u0 = *(const uint32_t*)(Res + r0 * 1024 + col);
                    uint32_t u1 = *(const uint32_t*)(Res + (r0 + 8) * 1024 + col);
                    __half2 a0 = __hadd2(*(__half2*)&v0, *(__half2*)&u0);
                    __half2 a1 = __hadd2(*(__half2*)&v1, *(__half2*)&u1);
                    v0 = *(uint32_t*)&a0;
                    v1 = *(uint32_t*)&a1;
                }
                *(uint32_t*)(D + r0 * 1024 + col)       = v0;
                *(uint32_t*)(D + (r0 + 8) * 1024 + col) = v1;
            }
        }
    } else {
        // Fused-logits epilogue: out = acc + res; dot with f16 Wf; per-warp
        // atomics (no smem reduce).
        float a0 = 0.f, a1 = 0.f;
        int bidx = (int)(row0 >> 11);   // 2048 rows per batch
#pragma unroll
        for (int mi = 0; mi < 2; mi++) {
            size_t r0 = row0 + mwarp0 + mi * 16 + (lane >> 2);
            int l0 = (int)(r0 & 2047);
#pragma unroll
            for (int nj = 0; nj < 8; nj++) {
                int col = colc + nwarp0 + nj * 8 + (lane & 3) * 2;
                uint32_t v0 = hacc[mi][nj][0];
                uint32_t v1 = hacc[mi][nj][1];
                uint32_t u0 = *(const uint32_t*)(Res + r0 * 1024 + col);
                uint32_t u1 = *(const uint32_t*)(Res + (r0 + 8) * 1024 + col);
                __half2 s0 = __hadd2(*(__half2*)&v0, *(__half2*)&u0);
                __half2 s1 = __hadd2(*(__half2*)&v1, *(__half2*)&u1);
                float2 f0 = __half22float2(s0);
                float2 f1 = __half22float2(s1);
                // g_wf16 rows [flat, 2]; uint2 covers (flat, flat+1) x 2 cls
                uint2 w0u = *(const uint2*)(g_wf16 + ((size_t)l0 * 1024 + col) * 2);
                uint2 w1u = *(const uint2*)(g_wf16 + ((size_t)(l0 + 8) * 1024 + col) * 2);
                float2 w00 = __half22float2(*(__half2*)&w0u.x);  // cls of col
                float2 w01 = __half22float2(*(__half2*)&w0u.y);  // cls of col+1
                float2 w10 = __half22float2(*(__half2*)&w1u.x);
                float2 w11 = __half22float2(*(__half2*)&w1u.y);
                a0 += f0.x * w00.x + f0.y * w01.x + f1.x * w10.x + f1.y * w11.x;
                a1 += f0.x * w00.y + f0.y * w01.y + f1.x * w10.y + f1.y * w11.y;
            }
        }
#pragma unroll
        for (int off = 16; off >= 1; off >>= 1) {
            a0 += __shfl_xor_sync(0xffffffffu, a0, off);
            a1 += __shfl_xor_sync(0xffffffffu, a1, off);
        }
        if (lane == 0) {
            atomicAdd(&g_logits[2 * bidx],     (double)a0);
            atomicAdd(&g_logits[2 * bidx + 1], (double)a1);
        }
    }
}

// ---------------------------------------------------------------------------
// 3) Attention on tensor cores (f16 in/out, f32 softmax accum).
// ---------------------------------------------------------------------------
#define ATT_WARPS 8
#define ATT_SMEM (ATT_WARPS * 3 * 4096)   // 96 KB
#define ROWSTRIDE_B (LSEQ * NHEAD * DHEAD * 2)  // batch-row stride in bytes

__global__ __launch_bounds__(256) void attn_kernel()
{
    extern __shared__ char asmem[];
    int t = threadIdx.x, w = t >> 5, lane = t & 31;
    uint32_t wbase = smem_to_u32(asmem) + w * 12288;
    uint32_t qsm = wbase, ksm = wbase + 4096, vsm = wbase + 8192;

    int pair = blockIdx.x * ATT_WARPS + w;
    int l = pair >> 4, n = pair & 15;
    size_t ebase = ((size_t)l * NHEAD + n) * DHEAD;
    const char* qg = (const char*)(g_qb + ebase);
    const char* kg = (const char*)(g_kb + ebase);
    const char* vg = (const char*)(g_vb + ebase);

#pragma unroll
    for (int i = 0; i < 8; i++) {
        int s = lane + 32 * i;
        int row = s >> 3, sub = s & 7;
        size_t go = (size_t)row * ROWSTRIDE_B + sub * 16;
        uint32_t so = SMEM_SWIZZLE_128B((uint32_t)(row * 128 + sub * 16));
        cp_async16(qsm + so, qg + go);
        cp_async16(ksm + so, kg + go);
        cp_async16(vsm + so, vg + go);
    }
    cp_commit();
    asm volatile("cp.async.wait_group 0;" ::: "memory");
    __syncwarp();

    int g8 = lane & 7, sel = lane >> 3;

    // ---- S = Q K^T ----
    float c[2][4][4];
#pragma unroll
    for (int mi = 0; mi < 2; mi++)
#pragma unroll
        for (int j = 0; j < 4; j++)
#pragma unroll
            for (int k = 0; k < 4; k++) c[mi][j][k] = 0.f;

#pragma unroll
    for (int kc = 0; kc < 4; kc++) {
        uint32_t kb = kc * 32;
        uint32_t af[2][4], bfr[2][4];
#pragma unroll
        for (int mi = 0; mi < 2; mi++) {
            int row = mi * 16 + g8 + (sel & 1) * 8;
            uint32_t off = row * 128 + ((kb + (sel >> 1) * 16) ^ ((row & 7) << 4));
            ldmx4(af[mi], qsm + off);
        }
#pragma unroll
        for (int nj2 = 0; nj2 < 2; nj2++) {
            int row = nj2 * 16 + g8 + (sel >> 1) * 8;
            uint32_t off = row * 128 + ((kb + (sel & 1) * 16) ^ ((row & 7) << 4));
            ldmx4(bfr[nj2], ksm + off);
        }
#pragma unroll
        for (int mi = 0; mi < 2; mi++)
#pragma unroll
            for (int nj2 = 0; nj2 < 2; nj2++) {
                mma16816f(c[mi][2 * nj2],     af[mi], &bfr[nj2][0]);
                mma16816f(c[mi][2 * nj2 + 1], af[mi], &bfr[nj2][2]);
            }
    }

    // ---- softmax ----
    float inv0[2], inv1[2];
#pragma unroll
    for (int mi = 0; mi < 2; mi++) {
        float m0 = -FLT_MAX, m1 = -FLT_MAX;
#pragma unroll
        for (int j = 0; j < 4; j++) {
#pragma unroll
            for (int k = 0; k < 4; k++) c[mi][j][k] *= 0.125f;
            m0 = fmaxf(m0, fmaxf(c[mi][j][0], c[mi][j][1]));
            m1 = fmaxf(m1, fmaxf(c[mi][j][2], c[mi][j][3]));
        }
        m0 = fmaxf(m0, __shfl_xor_sync(0xffffffffu, m0, 1));
        m0 = fmaxf(m0, __shfl_xor_sync(0xffffffffu, m0, 2));
        m1 = fmaxf(m1, __shfl_xor_sync(0xffffffffu, m1, 1));
        m1 = fmaxf(m1, __shfl_xor_sync(0xffffffffu, m1, 2));
        float s0 = 0.f, s1 = 0.f;
#pragma unroll
        for (int j = 0; j < 4; j++) {
            c[mi][j][0] = __expf(c[mi][j][0] - m0);
            c[mi][j][1] = __expf(c[mi][j][1] - m0);
            c[mi][j][2] = __expf(c[mi][j][2] - m1);
            c[mi][j][3] = __expf(c[mi][j][3] - m1);
            s0 += c[mi][j][0] + c[mi][j][1];
            s1 += c[mi][j][2] + c[mi][j][3];
        }
        s0 += __shfl_xor_sync(0xffffffffu, s0, 1);
        s0 += __shfl_xor_sync(0xffffffffu, s0, 2);
        s1 += __shfl_xor_sync(0xffffffffu, s1, 1);
        s1 += __shfl_xor_sync(0xffffffffu, s1, 2);
        inv0[mi] = 1.f / s0;
        inv1[mi] = 1.f / s1;
    }

    // ---- pack P ----
    uint32_t pf[2][2][4];
#pragma unroll
    for (int mi = 0; mi < 2; mi++)
#pragma unroll
        for (int kc = 0; kc < 2; kc++) {
            __half2 x0 = __floats2half2_rn(c[mi][2 * kc][0],     c[mi][2 * kc][1]);
            __half2 x1 = __floats2half2_rn(c[mi][2 * kc][2],     c[mi][2 * kc][3]);
            __half2 x2 = __floats2half2_rn(c[mi][2 * kc + 1][0], c[mi][2 * kc + 1][1]);
            __half2 x3 = __floats2half2_rn(c[mi][2 * kc + 1][2], c[mi][2 * kc + 1][3]);
            pf[mi][kc][0] = *(uint32_t*)&x0;
            pf[mi][kc][1] = *(uint32_t*)&x1;
            pf[mi][kc][2] = *(uint32_t*)&x2;
            pf[mi][kc][3] = *(uint32_t*)&x3;
        }

    // ---- att = P V ----
    float cv[2][8][4];
#pragma unroll
    for (int mi = 0; mi < 2; mi++)
#pragma unroll
        for (int j = 0; j < 8; j++)
#pragma unroll
            for (int k = 0; k < 4; k++) cv[mi][j][k] = 0.f;

#pragma unroll
    for (int kc = 0; kc < 2; kc++) {
#pragma unroll
        for (int dj2 = 0; dj2 < 4; dj2++) {
            int row = kc * 16 + g8 + (sel & 1) * 8;
            uint32_t colb = dj2 * 32 + (sel >> 1) * 16;
            uint32_t off = row * 128 + (colb ^ ((row & 7) << 4));
            uint32_t bv[4];
            ldmx4t(bv, vsm + off);
#pragma unroll
            for (int mi = 0; mi < 2; mi++) {
                mma16816f(cv[mi][2 * dj2],     pf[mi][kc], &bv[0]);
                mma16816f(cv[mi][2 * dj2 + 1], pf[mi][kc], &bv[2]);
            }
        }
    }

    // ---- normalize + store ----
    int r = lane >> 2, cq = (lane & 3) * 2;
#pragma unroll
    for (int mi = 0; mi < 2; mi++) {
        int i0 = mi * 16 + r;
        __half* o0 = g_qb + ebase + (size_t)i0 * (LSEQ * NHEAD * DHEAD);
        __half* o1 = o0 + (size_t)8 * (LSEQ * NHEAD * DHEAD);
#pragma unroll
        for (int dj = 0; dj < 8; dj++) {
            int col = dj * 8 + cq;
            __half2 h0 = __floats2half2_rn(cv[mi][dj][0] * inv0[mi],
                                           cv[mi][dj][1] * inv0[mi]);
            __half2 h1 = __floats2half2_rn(cv[mi][dj][2] * inv1[mi],
                                           cv[mi][dj][3] * inv1[mi]);
            *(uint32_t*)(o0 + col) = *(uint32_t*)&h0;
            *(uint32_t*)(o1 + col) = *(uint32_t*)&h1;
        }
    }
}

// ---------------------------------------------------------------------------
// 4) Loss
// ---------------------------------------------------------------------------
__global__ void loss_kernel(const int* __restrict__ y,
                            const float* __restrict__ bf,
                            float* __restrict__ out)
{
    if (threadIdx.x != 0 || blockIdx.x != 0) return;
    double s = 0.0;
    double b0 = (double)bf[0], b1 = (double)bf[1];
    for (int b = 0; b < BATCH; b++) {
        double l0 = g_logits[2 * b]     + b0;
        double l1 = g_logits[2 * b + 1] + b1;
        double m  = l0 > l1 ? l0 : l1;
        double lse = m + log(exp(l0 - m) + exp(l1 - m));
        double lp  = (y[b] == 0 ? l0 : l1) - lse;
        s += lp;
    }
    out[0] = (float)(-s / (double)BATCH);
}

// ---------------------------------------------------------------------------
// Launch
// ---------------------------------------------------------------------------
extern "C" void kernel_launch(void* const* d_in, const int* in_sizes, int n_in,
                              void* d_out, int out_size)
{
    const int*   x     = (const int*)d_in[0];
    const int*   y     = (const int*)d_in[1];
    const float* emb   = (const float*)d_in[2];
    const float* Wq    = (const float*)d_in[3];
    const float* Wkv   = (const float*)d_in[4];
    const float* Wo    = (const float*)d_in[5];
    const float* Wf    = (const float*)d_in[6];
    const float* bf    = (const float*)d_in[7];
    float* out = (float*)d_out;

    __half *p_hb, *p_qb, *p_kb, *p_vb, *p_wqkv, *p_wo;
    cudaGetSymbolAddress((void**)&p_hb,   g_hb);
    cudaGetSymbolAddress((void**)&p_qb,   g_qb);
    cudaGetSymbolAddress((void**)&p_kb,   g_kb);
    cudaGetSymbolAddress((void**)&p_vb,   g_vb);
    cudaGetSymbolAddress((void**)&p_wqkv, g_wqkv);
    cudaGetSymbolAddress((void**)&p_wo,   g_wo);

    cudaFuncSetAttribute((void*)gemm_f16_kernel<false, false>,
                         cudaFuncAttributeMaxDynamicSharedMemorySize, GEMM_SMEM);
    cudaFuncSetAttribute((void*)gemm_f16_kernel<true, true>,
                         cudaFuncAttributeMaxDynamicSharedMemorySize, GEMM_SMEM);
    cudaFuncSetAttribute(attn_kernel,
                         cudaFuncAttributeMaxDynamicSharedMemorySize, ATT_SMEM);

    // 1) merged prologue: transposes + logits zero + Wf f16 + gather
    prep_kernel<<<PREP_BLOCKS, 256>>>(x, emb, Wq, Wkv, Wo, Wf, p_wqkv, p_wo);

    // 2) fused QKV projection: one GEMM, N = 3072
    {
        int nx = 3 * EDIM / NT;              // 24
        gemm_f16_kernel<false, false><<<dim3(nx * (ROWS / MT), 1), 256, GEMM_SMEM>>>(
            p_hb, p_wqkv, nullptr, p_qb, p_kb, p_vb, nx);
    }

    // 3) attention (tensor cores; in place: g_qb <- att)
    attn_kernel<<<LSEQ * NHEAD / ATT_WARPS, 256, ATT_SMEM>>>();

    // 4) out = h + att @ Wo, fused with logits = out . Wf  (no g_ob)
    {
        int nx = EDIM / NT;                  // 8
        gemm_f16_kernel<true, true><<<dim3(nx * (ROWS / MT), 1), 256, GEMM_SMEM>>>(
            p_qb, p_wo, p_hb, nullptr, nullptr, nullptr, nx);
    }

    // 5) loss
    loss_kernel<<<1, 32>>>(y, bf, out);
}